// round 2
// baseline (speedup 1.0000x reference)
#include <cuda_runtime.h>
#include <cstdint>

// Problem constants
#define T_ 4
#define N_ 4096
#define D_ 64
#define E_ 2
#define CIN_ 192
#define H0_ 128
#define OUT_ 64
#define NC 72          // 64 aggr cols + 1 ones col + 7 pad
#define EPS_ 1e-12f

// GEMM tiling
#define BM 128
#define BK 32
#define AS 36          // padded smem stride for A (avoids bank conflicts)

// MLP tiling
#define NT 64          // nodes per block in fixup/MLP kernel
#define XS 196
#define HS 132

// Scratch (device globals; no allocation allowed)
__device__ float g_Bext[T_ * N_ * NC];        // node_feat + ones column, per t
__device__ float g_P[T_ * E_ * N_ * NC];      // raw GEMM results (incl row sums in col 64)
__device__ float g_W0T[CIN_ * H0_];           // w0 transposed [c][j]
__device__ float g_W1T[H0_ * OUT_];           // w1 transposed [c][o]

__device__ __forceinline__ unsigned f2tf(float f) {
    unsigned r;
    asm("cvt.rna.tf32.f32 %0, %1;" : "=r"(r) : "f"(f));
    return r;
}

// ---------------------------------------------------------------------------
// Prep: build Bext = [node | 1 | 0-pad], and transposed weights
// ---------------------------------------------------------------------------
__global__ void prep_kernel(const float* __restrict__ node,
                            const float* __restrict__ w0,
                            const float* __restrict__ w1) {
    int i = blockIdx.x * 256 + threadIdx.x;
    if (i < T_ * N_ * NC) {
        int c = i % NC;
        int tn = i / NC;
        float v = (c < D_) ? node[(size_t)tn * D_ + c] : (c == D_ ? 1.0f : 0.0f);
        g_Bext[i] = v;
    }
    if (i < CIN_ * H0_) {
        int c = i / H0_, j = i % H0_;
        g_W0T[i] = w0[(size_t)j * CIN_ + c];
    }
    if (i < H0_ * OUT_) {
        int c = i / OUT_, o = i % OUT_;
        g_W1T[i] = w1[(size_t)o * H0_ + c];
    }
}

// ---------------------------------------------------------------------------
// Main GEMM: P[t,e] = edge[t,e] (4096x4096) @ Bext[t] (4096x72), tf32 mma.sync
// grid = (N_/BM, T_*E_), 128 threads (4 warps), warp tile = 32 rows x 72 cols
// ---------------------------------------------------------------------------
__global__ void __launch_bounds__(128) gemm_edge_kernel(const float* __restrict__ edge) {
    __shared__ unsigned sA[BM * AS];   // 18432 B
    __shared__ unsigned sB[BK * NC];   // 9216 B

    const int te = blockIdx.y;                 // t*E + e
    const int t = te / E_;
    const int rowBase = blockIdx.x * BM;

    const float* __restrict__ Arow = edge + (size_t)te * N_ * N_ + (size_t)rowBase * N_;
    const float* __restrict__ Bbase = g_Bext + (size_t)t * N_ * NC;

    const int tid = threadIdx.x;
    const int warp = tid >> 5;
    const int lane = tid & 31;

    float acc[2][9][4];
#pragma unroll
    for (int mt = 0; mt < 2; mt++)
#pragma unroll
        for (int j = 0; j < 9; j++)
#pragma unroll
            for (int q = 0; q < 4; q++) acc[mt][j][q] = 0.0f;

    const int ar = tid >> 3;            // 0..15 row within group of 16
    const int akc = (tid & 7) * 4;      // float4 column

    for (int k0 = 0; k0 < N_; k0 += BK) {
        // --- load A tile 128x32, coalesced float4, convert to tf32 at STS ---
#pragma unroll
        for (int rr = 0; rr < BM; rr += 16) {
            const float4 v = *reinterpret_cast<const float4*>(
                Arow + (size_t)(rr + ar) * N_ + k0 + akc);
            unsigned* dst = &sA[(rr + ar) * AS + akc];
            dst[0] = f2tf(v.x); dst[1] = f2tf(v.y);
            dst[2] = f2tf(v.z); dst[3] = f2tf(v.w);
        }
        // --- load B tile 32x72 (contiguous, coalesced) ---
        {
            const float* bsrc = Bbase + (size_t)k0 * NC;
#pragma unroll
            for (int i = tid; i < BK * NC; i += 128) sB[i] = f2tf(bsrc[i]);
        }
        __syncthreads();

#pragma unroll
        for (int ks = 0; ks < 4; ks++) {
            const int kb = ks * 8;
            unsigned b0[9], b1[9];
#pragma unroll
            for (int j = 0; j < 9; j++) {
                b0[j] = sB[(kb + (lane & 3)) * NC + j * 8 + (lane >> 2)];
                b1[j] = sB[(kb + (lane & 3) + 4) * NC + j * 8 + (lane >> 2)];
            }
#pragma unroll
            for (int mt = 0; mt < 2; mt++) {
                const int rbase = warp * 32 + mt * 16;
                unsigned a0 = sA[(rbase + (lane >> 2)) * AS + kb + (lane & 3)];
                unsigned a1 = sA[(rbase + (lane >> 2) + 8) * AS + kb + (lane & 3)];
                unsigned a2 = sA[(rbase + (lane >> 2)) * AS + kb + (lane & 3) + 4];
                unsigned a3 = sA[(rbase + (lane >> 2) + 8) * AS + kb + (lane & 3) + 4];
#pragma unroll
                for (int j = 0; j < 9; j++) {
                    asm volatile(
                        "mma.sync.aligned.m16n8k8.row.col.f32.tf32.tf32.f32 "
                        "{%0,%1,%2,%3}, {%4,%5,%6,%7}, {%8,%9}, {%0,%1,%2,%3};\n"
                        : "+f"(acc[mt][j][0]), "+f"(acc[mt][j][1]),
                          "+f"(acc[mt][j][2]), "+f"(acc[mt][j][3])
                        : "r"(a0), "r"(a1), "r"(a2), "r"(a3),
                          "r"(b0[j]), "r"(b1[j]));
                }
            }
        }
        __syncthreads();
    }

    // --- epilogue: write P (float2 per fragment row) ---
    float* Pout = g_P + (size_t)te * N_ * NC;
#pragma unroll
    for (int mt = 0; mt < 2; mt++) {
        const int r0 = rowBase + warp * 32 + mt * 16 + (lane >> 2);
#pragma unroll
        for (int j = 0; j < 9; j++) {
            const int c = j * 8 + (lane & 3) * 2;
            *reinterpret_cast<float2*>(Pout + (size_t)r0 * NC + c) =
                make_float2(acc[mt][j][0], acc[mt][j][1]);
            *reinterpret_cast<float2*>(Pout + (size_t)(r0 + 8) * NC + c) =
                make_float2(acc[mt][j][2], acc[mt][j][3]);
        }
    }
}

// ---------------------------------------------------------------------------
// Fixup (diagonal removal + L1 normalize) fused with the 2-layer MLP.
// grid = T_*N_/NT blocks, 256 threads. Weights read via gmem (L1/L2 resident,
// coalesced through transposed copies).
// ---------------------------------------------------------------------------
__global__ void __launch_bounds__(256) fixup_mlp_kernel(const float* __restrict__ node,
                                                        const float* __restrict__ edge,
                                                        float* __restrict__ out) {
    extern __shared__ float sm[];
    float* SX = sm;                       // NT * XS
    float* SH = SX + NT * XS;             // NT * HS
    float* sdiag = SH + NT * HS;          // E_ * NT
    float* sinv = sdiag + E_ * NT;        // E_ * NT

    const int tid = threadIdx.x;
    const int blk = blockIdx.x;
    const int t = blk / (N_ / NT);
    const int nbase = (blk % (N_ / NT)) * NT;

    // per-(e,node): diagonal value and 1/denominator
    if (tid < E_ * NT) {
        const int e = tid / NT, i = tid % NT;
        const int n = nbase + i;
        const size_t teN = ((size_t)(t * E_ + e)) * N_;
        const float dg = edge[(teN + n) * N_ + n];
        const float denom = g_P[(teN + n) * NC + D_] - dg;
        sdiag[tid] = dg;
        sinv[tid] = 1.0f / fmaxf(denom, EPS_);
    }
    __syncthreads();

    // build X = [node | aggr_e0 | aggr_e1]
    for (int idx = tid; idx < NT * CIN_; idx += 256) {
        const int i = idx / CIN_, c = idx % CIN_;
        const int n = nbase + i;
        float v;
        if (c < D_) {
            v = node[((size_t)t * N_ + n) * D_ + c];
        } else {
            const int e = (c - D_) >> 6, d = (c - D_) & 63;
            const float nd = node[((size_t)t * N_ + n) * D_ + d];
            const float p = g_P[(((size_t)(t * E_ + e)) * N_ + n) * NC + d];
            v = (p - sdiag[e * NT + i] * nd) * sinv[e * NT + i];
        }
        SX[i * XS + c] = v;
    }
    __syncthreads();

    const int warp = tid >> 5;
    const int lane = tid & 31;

    // layer 0: h = leaky(X @ W0^T); warp handles 8 nodes, lane handles 4 j's
    {
        float acc[4][8];
#pragma unroll
        for (int jg = 0; jg < 4; jg++)
#pragma unroll
            for (int i = 0; i < 8; i++) acc[jg][i] = 0.0f;

#pragma unroll 2
        for (int c = 0; c < CIN_; c++) {
            float wv[4];
#pragma unroll
            for (int jg = 0; jg < 4; jg++)
                wv[jg] = g_W0T[c * H0_ + jg * 32 + lane];
#pragma unroll
            for (int i = 0; i < 8; i++) {
                const float xv = SX[(warp * 8 + i) * XS + c];
#pragma unroll
                for (int jg = 0; jg < 4; jg++)
                    acc[jg][i] = fmaf(wv[jg], xv, acc[jg][i]);
            }
        }
#pragma unroll
        for (int i = 0; i < 8; i++)
#pragma unroll
            for (int jg = 0; jg < 4; jg++) {
                float h = acc[jg][i];
                h = (h > 0.0f) ? h : 0.01f * h;
                SH[(warp * 8 + i) * HS + jg * 32 + lane] = h;
            }
    }
    __syncthreads();

    // layer 1: out = leaky(H @ W1^T); lane handles o = lane, lane+32
    {
        float acc[2][8];
#pragma unroll
        for (int og = 0; og < 2; og++)
#pragma unroll
            for (int i = 0; i < 8; i++) acc[og][i] = 0.0f;

#pragma unroll 2
        for (int c = 0; c < H0_; c++) {
            const float wv0 = g_W1T[c * OUT_ + lane];
            const float wv1 = g_W1T[c * OUT_ + 32 + lane];
#pragma unroll
            for (int i = 0; i < 8; i++) {
                const float hv = SH[(warp * 8 + i) * HS + c];
                acc[0][i] = fmaf(wv0, hv, acc[0][i]);
                acc[1][i] = fmaf(wv1, hv, acc[1][i]);
            }
        }
#pragma unroll
        for (int i = 0; i < 8; i++) {
            const int n = nbase + warp * 8 + i;
            float o0 = acc[0][i]; o0 = (o0 > 0.0f) ? o0 : 0.01f * o0;
            float o1 = acc[1][i]; o1 = (o1 > 0.0f) ? o1 : 0.01f * o1;
            out[((size_t)t * N_ + n) * OUT_ + lane] = o0;
            out[((size_t)t * N_ + n) * OUT_ + 32 + lane] = o1;
        }
    }
}

// ---------------------------------------------------------------------------
extern "C" void kernel_launch(void* const* d_in, const int* in_sizes, int n_in,
                              void* d_out, int out_size) {
    const float* node = nullptr;
    const float* edge = nullptr;
    const float* w0 = nullptr;
    const float* w1 = nullptr;
    for (int i = 0; i < n_in; i++) {
        const int s = in_sizes[i];
        if (s == T_ * N_ * D_)            node = (const float*)d_in[i];
        else if (s == T_ * E_ * N_ * N_)  edge = (const float*)d_in[i];
        else if (s == H0_ * CIN_)         w0 = (const float*)d_in[i];
        else if (s == OUT_ * H0_)         w1 = (const float*)d_in[i];
    }

    // prep: Bext + transposed weights
    {
        const int total = T_ * N_ * NC;
        prep_kernel<<<(total + 255) / 256, 256>>>(node, w0, w1);
    }
    // main tf32 GEMM over edge matrices
    {
        dim3 grid(N_ / BM, T_ * E_);
        gemm_edge_kernel<<<grid, 128>>>(edge);
    }
    // fixup + MLP
    {
        const size_t smem = (size_t)(NT * XS + NT * HS + 2 * E_ * NT) * sizeof(float);
        cudaFuncSetAttribute(fixup_mlp_kernel,
                             cudaFuncAttributeMaxDynamicSharedMemorySize, (int)smem);
        fixup_mlp_kernel<<<(T_ * N_) / NT, 256, smem>>>(node, edge, (float*)d_out);
    }
}

// round 3
// speedup vs baseline: 1.3957x; 1.3957x over previous
#include <cuda_runtime.h>
#include <cstdint>

// Problem constants
#define T_ 4
#define N_ 4096
#define D_ 64
#define E_ 2
#define CIN_ 192
#define H0_ 128
#define OUT_ 64
#define NC 72          // 64 aggr cols + 1 ones col + 7 pad
#define EPS_ 1e-12f

// GEMM tiling
#define BM 256
#define BK 32
#define AS 36          // padded smem row stride for A (conflict-free)
#define STAGES 4

// MLP tiling
#define NT 64
#define XS 196
#define HS 132

// Scratch (device globals; no allocation allowed)
__device__ float g_Bext[T_ * N_ * NC];        // node_feat + ones column (tf32-rounded bits)
__device__ float g_P[T_ * E_ * N_ * NC];      // raw GEMM results (row sums in col 64)
__device__ float g_W0T[CIN_ * H0_];
__device__ float g_W1T[H0_ * OUT_];

__device__ __forceinline__ unsigned f2tf(float f) {
    unsigned r;
    asm("cvt.rna.tf32.f32 %0, %1;" : "=r"(r) : "f"(f));
    return r;
}

__device__ __forceinline__ void cp16(void* dst_smem, const void* src_gmem) {
    unsigned d = (unsigned)__cvta_generic_to_shared(dst_smem);
    asm volatile("cp.async.cg.shared.global [%0], [%1], 16;\n" :: "r"(d), "l"(src_gmem));
}

// ---------------------------------------------------------------------------
// Prep: Bext = [tf32(node) | 1 | 0-pad], transposed weights
// ---------------------------------------------------------------------------
__global__ void prep_kernel(const float* __restrict__ node,
                            const float* __restrict__ w0,
                            const float* __restrict__ w1) {
    int i = blockIdx.x * 256 + threadIdx.x;
    if (i < T_ * N_ * NC) {
        int c = i % NC;
        int tn = i / NC;
        float v = (c < D_) ? node[(size_t)tn * D_ + c] : (c == D_ ? 1.0f : 0.0f);
        g_Bext[i] = __uint_as_float(f2tf(v));   // pre-round B to tf32 (RNA)
    }
    if (i < CIN_ * H0_) {
        int c = i / H0_, j = i % H0_;
        g_W0T[i] = w0[(size_t)j * CIN_ + c];
    }
    if (i < H0_ * OUT_) {
        int c = i / OUT_, o = i % OUT_;
        g_W1T[i] = w1[(size_t)o * H0_ + c];
    }
}

// ---------------------------------------------------------------------------
// Main GEMM: P[t,e] = edge[t,e] (4096x4096) @ Bext[t] (4096x72)
// BM=256 rows/CTA, 256 threads (8 warps, 32 rows each), cp.async 4-stage pipe.
// A operands fed as raw fp32 bits to mma.tf32 (HW truncates mantissa).
// grid = (16, 8) = 128 CTAs = one wave.
// ---------------------------------------------------------------------------
__global__ void __launch_bounds__(256, 1) gemm_edge_kernel(const float* __restrict__ edge) {
    extern __shared__ unsigned smem[];
    unsigned* sA = smem;                          // [STAGES][BM*AS]
    unsigned* sB = smem + STAGES * BM * AS;       // [STAGES][BK*NC]

    const int te = blockIdx.y;
    const int t = te / E_;
    const int rowBase = blockIdx.x * BM;

    const float* __restrict__ Arow = edge + (size_t)te * N_ * N_ + (size_t)rowBase * N_;
    const float* __restrict__ Bbase = g_Bext + (size_t)t * N_ * NC;

    const int tid = threadIdx.x;
    const int warp = tid >> 5;
    const int lane = tid & 31;

    // A-load mapping: 256 threads cover 32 rows x 32 cols (8 float4/row) per pass
    const int arow = tid >> 3;
    const int acol = (tid & 7) * 4;

    float acc[2][9][4];
#pragma unroll
    for (int mt = 0; mt < 2; mt++)
#pragma unroll
        for (int j = 0; j < 9; j++)
#pragma unroll
            for (int q = 0; q < 4; q++) acc[mt][j][q] = 0.0f;

    const int KT = N_ / BK;  // 128

    auto load_stage = [&](int s, int k0) {
        unsigned* dA = sA + s * (BM * AS);
        unsigned* dB = sB + s * (BK * NC);
#pragma unroll
        for (int rr = 0; rr < BM; rr += 32) {
            cp16(&dA[(rr + arow) * AS + acol],
                 Arow + (size_t)(rr + arow) * N_ + k0 + acol);
        }
        // B: 32x72 floats = 576 16B-chunks
        for (int c = tid; c < (BK * NC) / 4; c += 256) {
            int br = c / (NC / 4), bc = (c % (NC / 4)) * 4;
            cp16(&dB[br * NC + bc], Bbase + (size_t)(k0 + br) * NC + bc);
        }
    };

    // prologue: fill STAGES-1 stages
#pragma unroll
    for (int s = 0; s < STAGES - 1; s++) {
        load_stage(s, s * BK);
        asm volatile("cp.async.commit_group;\n");
    }

    for (int i = 0; i < KT; i++) {
        asm volatile("cp.async.wait_group %0;\n" :: "n"(STAGES - 2));
        __syncthreads();

        // prefetch into the stage consumed last iteration
        const int pf = i + STAGES - 1;
        if (pf < KT) load_stage(pf % STAGES, pf * BK);
        asm volatile("cp.async.commit_group;\n");

        // compute stage i % STAGES
        const unsigned* A = sA + (i % STAGES) * (BM * AS);
        const unsigned* B = sB + (i % STAGES) * (BK * NC);
#pragma unroll
        for (int ks = 0; ks < 4; ks++) {
            const int kb = ks * 8;
            unsigned b0[9], b1[9];
#pragma unroll
            for (int j = 0; j < 9; j++) {
                b0[j] = B[(kb + (lane & 3)) * NC + j * 8 + (lane >> 2)];
                b1[j] = B[(kb + (lane & 3) + 4) * NC + j * 8 + (lane >> 2)];
            }
#pragma unroll
            for (int mt = 0; mt < 2; mt++) {
                const int rbase = warp * 32 + mt * 16;
                unsigned a0 = A[(rbase + (lane >> 2)) * AS + kb + (lane & 3)];
                unsigned a1 = A[(rbase + (lane >> 2) + 8) * AS + kb + (lane & 3)];
                unsigned a2 = A[(rbase + (lane >> 2)) * AS + kb + (lane & 3) + 4];
                unsigned a3 = A[(rbase + (lane >> 2) + 8) * AS + kb + (lane & 3) + 4];
#pragma unroll
                for (int j = 0; j < 9; j++) {
                    asm volatile(
                        "mma.sync.aligned.m16n8k8.row.col.f32.tf32.tf32.f32 "
                        "{%0,%1,%2,%3}, {%4,%5,%6,%7}, {%8,%9}, {%0,%1,%2,%3};\n"
                        : "+f"(acc[mt][j][0]), "+f"(acc[mt][j][1]),
                          "+f"(acc[mt][j][2]), "+f"(acc[mt][j][3])
                        : "r"(a0), "r"(a1), "r"(a2), "r"(a3),
                          "r"(b0[j]), "r"(b1[j]));
                }
            }
        }
    }

    // epilogue
    float* Pout = g_P + (size_t)te * N_ * NC;
#pragma unroll
    for (int mt = 0; mt < 2; mt++) {
        const int r0 = rowBase + warp * 32 + mt * 16 + (lane >> 2);
#pragma unroll
        for (int j = 0; j < 9; j++) {
            const int c = j * 8 + (lane & 3) * 2;
            *reinterpret_cast<float2*>(Pout + (size_t)r0 * NC + c) =
                make_float2(acc[mt][j][0], acc[mt][j][1]);
            *reinterpret_cast<float2*>(Pout + (size_t)(r0 + 8) * NC + c) =
                make_float2(acc[mt][j][2], acc[mt][j][3]);
        }
    }
}

// ---------------------------------------------------------------------------
// Fixup (diagonal removal + L1 normalize) fused with the 2-layer MLP.
// ---------------------------------------------------------------------------
__global__ void __launch_bounds__(256) fixup_mlp_kernel(const float* __restrict__ node,
                                                        const float* __restrict__ edge,
                                                        float* __restrict__ out) {
    extern __shared__ float sm[];
    float* SX = sm;                       // NT * XS
    float* SH = SX + NT * XS;             // NT * HS
    float* sdiag = SH + NT * HS;          // E_ * NT
    float* sinv = sdiag + E_ * NT;        // E_ * NT

    const int tid = threadIdx.x;
    const int blk = blockIdx.x;
    const int t = blk / (N_ / NT);
    const int nbase = (blk % (N_ / NT)) * NT;

    if (tid < E_ * NT) {
        const int e = tid / NT, i = tid % NT;
        const int n = nbase + i;
        const size_t teN = ((size_t)(t * E_ + e)) * N_;
        const float dg = edge[(teN + n) * N_ + n];
        const float denom = g_P[(teN + n) * NC + D_] - dg;
        sdiag[tid] = dg;
        sinv[tid] = 1.0f / fmaxf(denom, EPS_);
    }
    __syncthreads();

    for (int idx = tid; idx < NT * CIN_; idx += 256) {
        const int i = idx / CIN_, c = idx % CIN_;
        const int n = nbase + i;
        float v;
        if (c < D_) {
            v = node[((size_t)t * N_ + n) * D_ + c];
        } else {
            const int e = (c - D_) >> 6, d = (c - D_) & 63;
            const float nd = node[((size_t)t * N_ + n) * D_ + d];
            const float p = g_P[(((size_t)(t * E_ + e)) * N_ + n) * NC + d];
            v = (p - sdiag[e * NT + i] * nd) * sinv[e * NT + i];
        }
        SX[i * XS + c] = v;
    }
    __syncthreads();

    const int warp = tid >> 5;
    const int lane = tid & 31;

    // layer 0
    {
        float acc[4][8];
#pragma unroll
        for (int jg = 0; jg < 4; jg++)
#pragma unroll
            for (int i = 0; i < 8; i++) acc[jg][i] = 0.0f;

#pragma unroll 2
        for (int c = 0; c < CIN_; c++) {
            float wv[4];
#pragma unroll
            for (int jg = 0; jg < 4; jg++)
                wv[jg] = g_W0T[c * H0_ + jg * 32 + lane];
#pragma unroll
            for (int i = 0; i < 8; i++) {
                const float xv = SX[(warp * 8 + i) * XS + c];
#pragma unroll
                for (int jg = 0; jg < 4; jg++)
                    acc[jg][i] = fmaf(wv[jg], xv, acc[jg][i]);
            }
        }
#pragma unroll
        for (int i = 0; i < 8; i++)
#pragma unroll
            for (int jg = 0; jg < 4; jg++) {
                float h = acc[jg][i];
                h = (h > 0.0f) ? h : 0.01f * h;
                SH[(warp * 8 + i) * HS + jg * 32 + lane] = h;
            }
    }
    __syncthreads();

    // layer 1
    {
        float acc[2][8];
#pragma unroll
        for (int og = 0; og < 2; og++)
#pragma unroll
            for (int i = 0; i < 8; i++) acc[og][i] = 0.0f;

#pragma unroll 2
        for (int c = 0; c < H0_; c++) {
            const float wv0 = g_W1T[c * OUT_ + lane];
            const float wv1 = g_W1T[c * OUT_ + 32 + lane];
#pragma unroll
            for (int i = 0; i < 8; i++) {
                const float hv = SH[(warp * 8 + i) * HS + c];
                acc[0][i] = fmaf(wv0, hv, acc[0][i]);
                acc[1][i] = fmaf(wv1, hv, acc[1][i]);
            }
        }
#pragma unroll
        for (int i = 0; i < 8; i++) {
            const int n = nbase + warp * 8 + i;
            float o0 = acc[0][i]; o0 = (o0 > 0.0f) ? o0 : 0.01f * o0;
            float o1 = acc[1][i]; o1 = (o1 > 0.0f) ? o1 : 0.01f * o1;
            out[((size_t)t * N_ + n) * OUT_ + lane] = o0;
            out[((size_t)t * N_ + n) * OUT_ + 32 + lane] = o1;
        }
    }
}

// ---------------------------------------------------------------------------
extern "C" void kernel_launch(void* const* d_in, const int* in_sizes, int n_in,
                              void* d_out, int out_size) {
    const float* node = nullptr;
    const float* edge = nullptr;
    const float* w0 = nullptr;
    const float* w1 = nullptr;
    for (int i = 0; i < n_in; i++) {
        const int s = in_sizes[i];
        if (s == T_ * N_ * D_)            node = (const float*)d_in[i];
        else if (s == T_ * E_ * N_ * N_)  edge = (const float*)d_in[i];
        else if (s == H0_ * CIN_)         w0 = (const float*)d_in[i];
        else if (s == OUT_ * H0_)         w1 = (const float*)d_in[i];
    }

    {
        const int total = T_ * N_ * NC;
        prep_kernel<<<(total + 255) / 256, 256>>>(node, w0, w1);
    }
    {
        const size_t smem = (size_t)STAGES * (BM * AS + BK * NC) * sizeof(unsigned);
        cudaFuncSetAttribute(gemm_edge_kernel,
                             cudaFuncAttributeMaxDynamicSharedMemorySize, (int)smem);
        dim3 grid(N_ / BM, T_ * E_);
        gemm_edge_kernel<<<grid, 256, smem>>>(edge);
    }
    {
        const size_t smem = (size_t)(NT * XS + NT * HS + 2 * E_ * NT) * sizeof(float);
        cudaFuncSetAttribute(fixup_mlp_kernel,
                             cudaFuncAttributeMaxDynamicSharedMemorySize, (int)smem);
        fixup_mlp_kernel<<<(T_ * N_) / NT, 256, smem>>>(node, edge, (float*)d_out);
    }
}

// round 5
// speedup vs baseline: 1.4566x; 1.0436x over previous
#include <cuda_runtime.h>
#include <cstdint>

// Problem constants
#define T_ 4
#define N_ 4096
#define D_ 64
#define E_ 2
#define CIN_ 192
#define H0_ 128
#define OUT_ 64
#define NC 72          // 64 aggr cols + 1 ones col + 7 pad
#define EPS_ 1e-12f

// GEMM tiling
#define BM 128
#define BK 32
#define AS 36          // padded smem row stride for A (conflict-free)
#define STAGES 4

// MLP tiling
#define NT 64
#define XS 196
#define HS 132

// Scratch (device globals; no allocation allowed)
__device__ float g_Bext[T_ * N_ * NC];        // node_feat + ones column (tf32-rounded bits)
__device__ float g_P[T_ * E_ * N_ * NC];      // raw GEMM results (row sums in col 64)
__device__ float g_W0T[CIN_ * H0_];
__device__ float g_W1T[H0_ * OUT_];

__device__ __forceinline__ unsigned f2tf(float f) {
    unsigned r;
    asm("cvt.rna.tf32.f32 %0, %1;" : "=r"(r) : "f"(f));
    return r;
}

__device__ __forceinline__ void cp16(void* dst_smem, const void* src_gmem) {
    unsigned d = (unsigned)__cvta_generic_to_shared(dst_smem);
    asm volatile("cp.async.cg.shared.global [%0], [%1], 16;\n" :: "r"(d), "l"(src_gmem));
}

// ---------------------------------------------------------------------------
// Prep: Bext = [tf32(node) | 1 | 0-pad], transposed weights
// ---------------------------------------------------------------------------
__global__ void prep_kernel(const float* __restrict__ node,
                            const float* __restrict__ w0,
                            const float* __restrict__ w1) {
    int i = blockIdx.x * 256 + threadIdx.x;
    if (i < T_ * N_ * NC) {
        int c = i % NC;
        int tn = i / NC;
        float v = (c < D_) ? node[(size_t)tn * D_ + c] : (c == D_ ? 1.0f : 0.0f);
        g_Bext[i] = __uint_as_float(f2tf(v));   // pre-round B to tf32 (RNA)
    }
    if (i < CIN_ * H0_) {
        int c = i / H0_, j = i % H0_;
        g_W0T[i] = w0[(size_t)j * CIN_ + c];
    }
    if (i < H0_ * OUT_) {
        int c = i / OUT_, o = i % OUT_;
        g_W1T[i] = w1[(size_t)o * H0_ + c];
    }
}

// ---------------------------------------------------------------------------
// Main GEMM: P[t,e] = edge[t,e] (4096x4096) @ Bext[t] (4096x72)
// BM=128 rows/CTA, 128 threads (4 warps, 32 rows each), cp.async 4-stage pipe.
// Smem = 110.6 KB -> 2 CTAs/SM = 8 warps/SM for latency hiding.
// grid = (32, 8) = 256 CTAs.
// ---------------------------------------------------------------------------
__global__ void __launch_bounds__(128, 2) gemm_edge_kernel(const float* __restrict__ edge) {
    extern __shared__ unsigned smem[];
    unsigned* sA = smem;                          // [STAGES][BM*AS]
    unsigned* sB = smem + STAGES * BM * AS;       // [STAGES][BK*NC]

    const int te = blockIdx.y;
    const int t = te / E_;
    const int rowBase = blockIdx.x * BM;

    const float* __restrict__ Arow = edge + (size_t)te * N_ * N_ + (size_t)rowBase * N_;
    const float* __restrict__ Bbase = g_Bext + (size_t)t * N_ * NC;

    const int tid = threadIdx.x;
    const int warp = tid >> 5;
    const int lane = tid & 31;

    // A-load mapping: 128 threads cover 16 rows x 32 cols (8 float4/row) per pass
    const int arow = tid >> 3;          // 0..15
    const int acol = (tid & 7) * 4;

    float acc[2][9][4];
#pragma unroll
    for (int mt = 0; mt < 2; mt++)
#pragma unroll
        for (int j = 0; j < 9; j++)
#pragma unroll
            for (int q = 0; q < 4; q++) acc[mt][j][q] = 0.0f;

    const int KT = N_ / BK;  // 128

    auto load_stage = [&](int s, int k0) {
        unsigned* dA = sA + s * (BM * AS);
        unsigned* dB = sB + s * (BK * NC);
#pragma unroll
        for (int rr = 0; rr < BM; rr += 16) {
            cp16(&dA[(rr + arow) * AS + acol],
                 Arow + (size_t)(rr + arow) * N_ + k0 + acol);
        }
        // B: 32x72 floats = 576 16B-chunks
#pragma unroll
        for (int c = tid; c < (BK * NC) / 4; c += 128) {
            int br = c / (NC / 4), bc = (c % (NC / 4)) * 4;
            cp16(&dB[br * NC + bc], Bbase + (size_t)(k0 + br) * NC + bc);
        }
    };

    // prologue: fill STAGES-1 stages
#pragma unroll
    for (int s = 0; s < STAGES - 1; s++) {
        load_stage(s, s * BK);
        asm volatile("cp.async.commit_group;\n");
    }

    for (int i = 0; i < KT; i++) {
        asm volatile("cp.async.wait_group %0;\n" :: "n"(STAGES - 2));
        __syncthreads();

        // prefetch into the stage consumed last iteration
        const int pf = i + STAGES - 1;
        if (pf < KT) load_stage(pf % STAGES, pf * BK);
        asm volatile("cp.async.commit_group;\n");

        // compute stage i % STAGES
        const unsigned* A = sA + (i % STAGES) * (BM * AS);
        const unsigned* B = sB + (i % STAGES) * (BK * NC);
#pragma unroll
        for (int ks = 0; ks < 4; ks++) {
            const int kb = ks * 8;
            unsigned b0[9], b1[9];
#pragma unroll
            for (int j = 0; j < 9; j++) {
                b0[j] = B[(kb + (lane & 3)) * NC + j * 8 + (lane >> 2)];
                b1[j] = B[(kb + (lane & 3) + 4) * NC + j * 8 + (lane >> 2)];
            }
#pragma unroll
            for (int mt = 0; mt < 2; mt++) {
                const int rbase = warp * 32 + mt * 16;
                unsigned a0 = A[(rbase + (lane >> 2)) * AS + kb + (lane & 3)];
                unsigned a1 = A[(rbase + (lane >> 2) + 8) * AS + kb + (lane & 3)];
                unsigned a2 = A[(rbase + (lane >> 2)) * AS + kb + (lane & 3) + 4];
                unsigned a3 = A[(rbase + (lane >> 2) + 8) * AS + kb + (lane & 3) + 4];
#pragma unroll
                for (int j = 0; j < 9; j++) {
                    asm volatile(
                        "mma.sync.aligned.m16n8k8.row.col.f32.tf32.tf32.f32 "
                        "{%0,%1,%2,%3}, {%4,%5,%6,%7}, {%8,%9}, {%0,%1,%2,%3};\n"
                        : "+f"(acc[mt][j][0]), "+f"(acc[mt][j][1]),
                          "+f"(acc[mt][j][2]), "+f"(acc[mt][j][3])
                        : "r"(a0), "r"(a1), "r"(a2), "r"(a3),
                          "r"(b0[j]), "r"(b1[j]));
                }
            }
        }
    }

    // epilogue
    float* Pout = g_P + (size_t)te * N_ * NC;
#pragma unroll
    for (int mt = 0; mt < 2; mt++) {
        const int r0 = rowBase + warp * 32 + mt * 16 + (lane >> 2);
#pragma unroll
        for (int j = 0; j < 9; j++) {
            const int c = j * 8 + (lane & 3) * 2;
            *reinterpret_cast<float2*>(Pout + (size_t)r0 * NC + c) =
                make_float2(acc[mt][j][0], acc[mt][j][1]);
            *reinterpret_cast<float2*>(Pout + (size_t)(r0 + 8) * NC + c) =
                make_float2(acc[mt][j][2], acc[mt][j][3]);
        }
    }
}

// ---------------------------------------------------------------------------
// Fixup (diagonal removal + L1 normalize) fused with the 2-layer MLP.
// ---------------------------------------------------------------------------
__global__ void __launch_bounds__(256) fixup_mlp_kernel(const float* __restrict__ node,
                                                        const float* __restrict__ edge,
                                                        float* __restrict__ out) {
    extern __shared__ float sm[];
    float* SX = sm;                       // NT * XS
    float* SH = SX + NT * XS;             // NT * HS
    float* sdiag = SH + NT * HS;          // E_ * NT
    float* sinv = sdiag + E_ * NT;        // E_ * NT

    const int tid = threadIdx.x;
    const int blk = blockIdx.x;
    const int t = blk / (N_ / NT);
    const int nbase = (blk % (N_ / NT)) * NT;

    if (tid < E_ * NT) {
        const int e = tid / NT, i = tid % NT;
        const int n = nbase + i;
        const size_t teN = ((size_t)(t * E_ + e)) * N_;
        const float dg = edge[(teN + n) * N_ + n];
        const float denom = g_P[(teN + n) * NC + D_] - dg;
        sdiag[tid] = dg;
        sinv[tid] = 1.0f / fmaxf(denom, EPS_);
    }
    __syncthreads();

    for (int idx = tid; idx < NT * CIN_; idx += 256) {
        const int i = idx / CIN_, c = idx % CIN_;
        const int n = nbase + i;
        float v;
        if (c < D_) {
            v = node[((size_t)t * N_ + n) * D_ + c];
        } else {
            const int e = (c - D_) >> 6, d = (c - D_) & 63;
            const float nd = node[((size_t)t * N_ + n) * D_ + d];
            const float p = g_P[(((size_t)(t * E_ + e)) * N_ + n) * NC + d];
            v = (p - sdiag[e * NT + i] * nd) * sinv[e * NT + i];
        }
        SX[i * XS + c] = v;
    }
    __syncthreads();

    const int warp = tid >> 5;
    const int lane = tid & 31;

    // layer 0
    {
        float acc[4][8];
#pragma unroll
        for (int jg = 0; jg < 4; jg++)
#pragma unroll
            for (int i = 0; i < 8; i++) acc[jg][i] = 0.0f;

#pragma unroll 2
        for (int c = 0; c < CIN_; c++) {
            float wv[4];
#pragma unroll
            for (int jg = 0; jg < 4; jg++)
                wv[jg] = g_W0T[c * H0_ + jg * 32 + lane];
#pragma unroll
            for (int i = 0; i < 8; i++) {
                const float xv = SX[(warp * 8 + i) * XS + c];
#pragma unroll
                for (int jg = 0; jg < 4; jg++)
                    acc[jg][i] = fmaf(wv[jg], xv, acc[jg][i]);
            }
        }
#pragma unroll
        for (int i = 0; i < 8; i++)
#pragma unroll
            for (int jg = 0; jg < 4; jg++) {
                float h = acc[jg][i];
                h = (h > 0.0f) ? h : 0.01f * h;
                SH[(warp * 8 + i) * HS + jg * 32 + lane] = h;
            }
    }
    __syncthreads();

    // layer 1
    {
        float acc[2][8];
#pragma unroll
        for (int og = 0; og < 2; og++)
#pragma unroll
            for (int i = 0; i < 8; i++) acc[og][i] = 0.0f;

#pragma unroll 2
        for (int c = 0; c < H0_; c++) {
            const float wv0 = g_W1T[c * OUT_ + lane];
            const float wv1 = g_W1T[c * OUT_ + 32 + lane];
#pragma unroll
            for (int i = 0; i < 8; i++) {
                const float hv = SH[(warp * 8 + i) * HS + c];
                acc[0][i] = fmaf(wv0, hv, acc[0][i]);
                acc[1][i] = fmaf(wv1, hv, acc[1][i]);
            }
        }
#pragma unroll
        for (int i = 0; i < 8; i++) {
            const int n = nbase + warp * 8 + i;
            float o0 = acc[0][i]; o0 = (o0 > 0.0f) ? o0 : 0.01f * o0;
            float o1 = acc[1][i]; o1 = (o1 > 0.0f) ? o1 : 0.01f * o1;
            out[((size_t)t * N_ + n) * OUT_ + lane] = o0;
            out[((size_t)t * N_ + n) * OUT_ + 32 + lane] = o1;
        }
    }
}

// ---------------------------------------------------------------------------
extern "C" void kernel_launch(void* const* d_in, const int* in_sizes, int n_in,
                              void* d_out, int out_size) {
    const float* node = nullptr;
    const float* edge = nullptr;
    const float* w0 = nullptr;
    const float* w1 = nullptr;
    for (int i = 0; i < n_in; i++) {
        const int s = in_sizes[i];
        if (s == T_ * N_ * D_)            node = (const float*)d_in[i];
        else if (s == T_ * E_ * N_ * N_)  edge = (const float*)d_in[i];
        else if (s == H0_ * CIN_)         w0 = (const float*)d_in[i];
        else if (s == OUT_ * H0_)         w1 = (const float*)d_in[i];
    }

    {
        const int total = T_ * N_ * NC;
        prep_kernel<<<(total + 255) / 256, 256>>>(node, w0, w1);
    }
    {
        const size_t smem = (size_t)STAGES * (BM * AS + BK * NC) * sizeof(unsigned);
        cudaFuncSetAttribute(gemm_edge_kernel,
                             cudaFuncAttributeMaxDynamicSharedMemorySize, (int)smem);
        dim3 grid(N_ / BM, T_ * E_);
        gemm_edge_kernel<<<grid, 128, smem>>>(edge);
    }
    {
        const size_t smem = (size_t)(NT * XS + NT * HS + 2 * E_ * NT) * sizeof(float);
        cudaFuncSetAttribute(fixup_mlp_kernel,
                             cudaFuncAttributeMaxDynamicSharedMemorySize, (int)smem);
        fixup_mlp_kernel<<<(T_ * N_) / NT, 256, smem>>>(node, edge, (float*)d_out);
    }
}

// round 6
// speedup vs baseline: 1.6425x; 1.1277x over previous
#include <cuda_runtime.h>
#include <cuda_bf16.h>
#include <cstdint>

// Problem constants
#define T_ 4
#define N_ 4096
#define D_ 64
#define E_ 2
#define CIN_ 192
#define H0_ 128
#define OUT_ 64
#define NC 72          // 64 aggr cols + 1 ones col + 7 pad
#define EPS_ 1e-12f

// GEMM tiling
#define BM 128
#define BK 32
#define AS 40          // A smem row stride (floats) — conflict-free for LDS.64 pattern
#define BSW 20         // B smem row stride (bf16x2 words) — conflict-free
#define STAGES 4
#define THREADS 256
#define KT (N_ / BK)

// MLP tiling
#define NT 64
#define XS 196
#define HS 132

// Scratch (device globals; no allocation allowed)
__device__ __nv_bfloat16 g_BextB[T_ * NC * N_];  // [t][n(72)][k(4096)] bf16: node^T + ones row
__device__ float g_P[T_ * E_ * N_ * NC];         // GEMM results (row sums in col 64)
__device__ float g_W0T[CIN_ * H0_];
__device__ float g_W1T[H0_ * OUT_];

__device__ __forceinline__ void cp16(void* dst_smem, const void* src_gmem) {
    unsigned d = (unsigned)__cvta_generic_to_shared(dst_smem);
    asm volatile("cp.async.cg.shared.global [%0], [%1], 16;\n" :: "r"(d), "l"(src_gmem));
}
__device__ __forceinline__ unsigned packbf(float lo, float hi) {
    unsigned r;
    asm("cvt.rn.bf16x2.f32 %0, %1, %2;" : "=r"(r) : "f"(hi), "f"(lo));
    return r;
}

// ---------------------------------------------------------------------------
// prep_b: transpose node -> g_BextB [t][n][k] bf16, with ones row at n=64
// grid = T_*128 (each block: 32 k-rows), 256 threads
// ---------------------------------------------------------------------------
__global__ void __launch_bounds__(256) prep_b_kernel(const float* __restrict__ node) {
    __shared__ float s[32][65];
    const int t = blockIdx.x >> 7;
    const int k0 = (blockIdx.x & 127) * 32;
    const int tid = threadIdx.x;
    for (int i = tid; i < 32 * 64; i += THREADS) {
        int r = i >> 6, d = i & 63;
        s[r][d] = node[((size_t)t * N_ + k0 + r) * D_ + d];
    }
    __syncthreads();
    for (int o = tid; o < NC * 32; o += THREADS) {
        int n = o >> 5, kk = o & 31;
        float v = (n < D_) ? s[kk][n] : (n == D_ ? 1.0f : 0.0f);
        g_BextB[((size_t)t * NC + n) * N_ + k0 + kk] = __float2bfloat16_rn(v);
    }
}

// ---------------------------------------------------------------------------
// prep_w: transposed weight copies
// ---------------------------------------------------------------------------
__global__ void prep_w_kernel(const float* __restrict__ w0,
                              const float* __restrict__ w1) {
    int i = blockIdx.x * 256 + threadIdx.x;
    if (i < CIN_ * H0_) {
        int c = i / H0_, j = i % H0_;
        g_W0T[i] = w0[(size_t)j * CIN_ + c];
    }
    if (i < H0_ * OUT_) {
        int c = i / OUT_, o = i % OUT_;
        g_W1T[i] = w1[(size_t)o * H0_ + c];
    }
}

// ---------------------------------------------------------------------------
// Main GEMM: P[t,e] = edge[t,e] (4096x4096) @ Bext[t] (4096x72)
// bf16 m16n8k16, A fp32 in smem (packed to bf16 in regs), B bf16 in smem.
// 256 threads = 8 warps x 16-row tiles; 2 CTAs/SM -> 4 warps/SMSP.
// ---------------------------------------------------------------------------
__global__ void __launch_bounds__(256, 2) gemm_edge_kernel(const float* __restrict__ edge) {
    extern __shared__ unsigned smem[];
    float* sA = reinterpret_cast<float*>(smem);       // [STAGES][BM*AS]
    unsigned* sB = smem + STAGES * BM * AS;           // [STAGES][NC*BSW]

    const int te = blockIdx.y;
    const int t = te / E_;
    const int rowBase = blockIdx.x * BM;

    const float* __restrict__ Arow = edge + (size_t)te * N_ * N_ + (size_t)rowBase * N_;
    const __nv_bfloat16* __restrict__ Bbase = g_BextB + (size_t)t * NC * N_;

    const int tid = threadIdx.x;
    const int warp = tid >> 5;
    const int lane = tid & 31;
    const int g = lane >> 2;
    const int tq = lane & 3;

    const int arow = tid >> 3;          // 0..31
    const int acol = (tid & 7) * 4;

    float acc[9][4];
#pragma unroll
    for (int j = 0; j < 9; j++)
#pragma unroll
        for (int q = 0; q < 4; q++) acc[j][q] = 0.0f;

    auto load_stage = [&](int s, int k0) {
        float* dA = sA + s * (BM * AS);
        unsigned* dB = sB + s * (NC * BSW);
#pragma unroll
        for (int rr = 0; rr < BM; rr += 32) {
            cp16(&dA[(rr + arow) * AS + acol],
                 Arow + (size_t)(rr + arow) * N_ + k0 + acol);
        }
        // B: 72 rows x 64B (32 bf16) = 288 16B-chunks
        for (int c = tid; c < NC * 4; c += THREADS) {
            int row = c >> 2, ch = c & 3;
            cp16(dB + row * BSW + ch * 4, Bbase + (size_t)row * N_ + k0 + ch * 8);
        }
    };

#pragma unroll
    for (int s = 0; s < STAGES - 1; s++) {
        load_stage(s, s * BK);
        asm volatile("cp.async.commit_group;\n");
    }

    for (int i = 0; i < KT; i++) {
        asm volatile("cp.async.wait_group %0;\n" :: "n"(STAGES - 2));
        __syncthreads();

        const int pf = i + STAGES - 1;
        if (pf < KT) load_stage(pf % STAGES, pf * BK);
        asm volatile("cp.async.commit_group;\n");

        const float* A = sA + (i % STAGES) * (BM * AS);
        const unsigned* B = sB + (i % STAGES) * (NC * BSW);
        const int r0 = warp * 16 + g;

#pragma unroll
        for (int ks = 0; ks < 2; ks++) {
            const int kb = ks * 16;
            float2 v;
            v = *reinterpret_cast<const float2*>(&A[r0 * AS + kb + 2 * tq]);
            const unsigned a0 = packbf(v.x, v.y);
            v = *reinterpret_cast<const float2*>(&A[(r0 + 8) * AS + kb + 2 * tq]);
            const unsigned a1 = packbf(v.x, v.y);
            v = *reinterpret_cast<const float2*>(&A[r0 * AS + kb + 2 * tq + 8]);
            const unsigned a2 = packbf(v.x, v.y);
            v = *reinterpret_cast<const float2*>(&A[(r0 + 8) * AS + kb + 2 * tq + 8]);
            const unsigned a3 = packbf(v.x, v.y);
#pragma unroll
            for (int j = 0; j < 9; j++) {
                const unsigned b0 = B[(j * 8 + g) * BSW + ks * 8 + tq];
                const unsigned b1 = B[(j * 8 + g) * BSW + ks * 8 + tq + 4];
                asm volatile(
                    "mma.sync.aligned.m16n8k16.row.col.f32.bf16.bf16.f32 "
                    "{%0,%1,%2,%3}, {%4,%5,%6,%7}, {%8,%9}, {%0,%1,%2,%3};\n"
                    : "+f"(acc[j][0]), "+f"(acc[j][1]),
                      "+f"(acc[j][2]), "+f"(acc[j][3])
                    : "r"(a0), "r"(a1), "r"(a2), "r"(a3),
                      "r"(b0), "r"(b1));
            }
        }
    }

    // epilogue
    float* Pout = g_P + (size_t)te * N_ * NC;
    const int rg = rowBase + warp * 16 + g;
#pragma unroll
    for (int j = 0; j < 9; j++) {
        const int c = j * 8 + tq * 2;
        *reinterpret_cast<float2*>(Pout + (size_t)rg * NC + c) =
            make_float2(acc[j][0], acc[j][1]);
        *reinterpret_cast<float2*>(Pout + (size_t)(rg + 8) * NC + c) =
            make_float2(acc[j][2], acc[j][3]);
    }
}

// ---------------------------------------------------------------------------
// Fixup (diagonal removal + L1 normalize) fused with the 2-layer MLP.
// ---------------------------------------------------------------------------
__global__ void __launch_bounds__(256) fixup_mlp_kernel(const float* __restrict__ node,
                                                        const float* __restrict__ edge,
                                                        float* __restrict__ out) {
    extern __shared__ float sm[];
    float* SX = sm;                       // NT * XS
    float* SH = SX + NT * XS;             // NT * HS
    float* sdiag = SH + NT * HS;          // E_ * NT
    float* sinv = sdiag + E_ * NT;        // E_ * NT

    const int tid = threadIdx.x;
    const int blk = blockIdx.x;
    const int t = blk / (N_ / NT);
    const int nbase = (blk % (N_ / NT)) * NT;

    if (tid < E_ * NT) {
        const int e = tid / NT, i = tid % NT;
        const int n = nbase + i;
        const size_t teN = ((size_t)(t * E_ + e)) * N_;
        const float dgf = edge[(teN + n) * N_ + n];
        const float dg = __bfloat162float(__float2bfloat16_rn(dgf));  // match GEMM rounding
        const float denom = g_P[(teN + n) * NC + D_] - dg;
        sdiag[tid] = dg;
        sinv[tid] = 1.0f / fmaxf(denom, EPS_);
    }
    __syncthreads();

    for (int idx = tid; idx < NT * CIN_; idx += 256) {
        const int i = idx / CIN_, c = idx % CIN_;
        const int n = nbase + i;
        float v;
        if (c < D_) {
            v = node[((size_t)t * N_ + n) * D_ + c];
        } else {
            const int e = (c - D_) >> 6, d = (c - D_) & 63;
            const float nd = node[((size_t)t * N_ + n) * D_ + d];
            const float p = g_P[(((size_t)(t * E_ + e)) * N_ + n) * NC + d];
            v = (p - sdiag[e * NT + i] * nd) * sinv[e * NT + i];
        }
        SX[i * XS + c] = v;
    }
    __syncthreads();

    const int warp = tid >> 5;
    const int lane = tid & 31;

    // layer 0
    {
        float acc[4][8];
#pragma unroll
        for (int jg = 0; jg < 4; jg++)
#pragma unroll
            for (int i = 0; i < 8; i++) acc[jg][i] = 0.0f;

#pragma unroll 2
        for (int c = 0; c < CIN_; c++) {
            float wv[4];
#pragma unroll
            for (int jg = 0; jg < 4; jg++)
                wv[jg] = g_W0T[c * H0_ + jg * 32 + lane];
#pragma unroll
            for (int i = 0; i < 8; i++) {
                const float xv = SX[(warp * 8 + i) * XS + c];
#pragma unroll
                for (int jg = 0; jg < 4; jg++)
                    acc[jg][i] = fmaf(wv[jg], xv, acc[jg][i]);
            }
        }
#pragma unroll
        for (int i = 0; i < 8; i++)
#pragma unroll
            for (int jg = 0; jg < 4; jg++) {
                float h = acc[jg][i];
                h = (h > 0.0f) ? h : 0.01f * h;
                SH[(warp * 8 + i) * HS + jg * 32 + lane] = h;
            }
    }
    __syncthreads();

    // layer 1
    {
        float acc[2][8];
#pragma unroll
        for (int og = 0; og < 2; og++)
#pragma unroll
            for (int i = 0; i < 8; i++) acc[og][i] = 0.0f;

#pragma unroll 2
        for (int c = 0; c < H0_; c++) {
            const float wv0 = g_W1T[c * OUT_ + lane];
            const float wv1 = g_W1T[c * OUT_ + 32 + lane];
#pragma unroll
            for (int i = 0; i < 8; i++) {
                const float hv = SH[(warp * 8 + i) * HS + c];
                acc[0][i] = fmaf(wv0, hv, acc[0][i]);
                acc[1][i] = fmaf(wv1, hv, acc[1][i]);
            }
        }
#pragma unroll
        for (int i = 0; i < 8; i++) {
            const int n = nbase + warp * 8 + i;
            float o0 = acc[0][i]; o0 = (o0 > 0.0f) ? o0 : 0.01f * o0;
            float o1 = acc[1][i]; o1 = (o1 > 0.0f) ? o1 : 0.01f * o1;
            out[((size_t)t * N_ + n) * OUT_ + lane] = o0;
            out[((size_t)t * N_ + n) * OUT_ + 32 + lane] = o1;
        }
    }
}

// ---------------------------------------------------------------------------
extern "C" void kernel_launch(void* const* d_in, const int* in_sizes, int n_in,
                              void* d_out, int out_size) {
    const float* node = nullptr;
    const float* edge = nullptr;
    const float* w0 = nullptr;
    const float* w1 = nullptr;
    for (int i = 0; i < n_in; i++) {
        const int s = in_sizes[i];
        if (s == T_ * N_ * D_)            node = (const float*)d_in[i];
        else if (s == T_ * E_ * N_ * N_)  edge = (const float*)d_in[i];
        else if (s == H0_ * CIN_)         w0 = (const float*)d_in[i];
        else if (s == OUT_ * H0_)         w1 = (const float*)d_in[i];
    }

    prep_b_kernel<<<T_ * 128, THREADS>>>(node);
    prep_w_kernel<<<(CIN_ * H0_ + 255) / 256, 256>>>(w0, w1);

    {
        const size_t smem = (size_t)STAGES * (BM * AS + NC * BSW) * sizeof(unsigned);
        cudaFuncSetAttribute(gemm_edge_kernel,
                             cudaFuncAttributeMaxDynamicSharedMemorySize, (int)smem);
        dim3 grid(N_ / BM, T_ * E_);
        gemm_edge_kernel<<<grid, THREADS, smem>>>(edge);
    }
    {
        const size_t smem = (size_t)(NT * XS + NT * HS + 2 * E_ * NT) * sizeof(float);
        cudaFuncSetAttribute(fixup_mlp_kernel,
                             cudaFuncAttributeMaxDynamicSharedMemorySize, (int)smem);
        fixup_mlp_kernel<<<(T_ * N_) / NT, 256, smem>>>(node, edge, (float*)d_out);
    }
}

// round 7
// speedup vs baseline: 2.3737x; 1.4452x over previous
#include <cuda_runtime.h>
#include <cuda_bf16.h>
#include <cstdint>

// Problem constants
#define T_ 4
#define N_ 4096
#define D_ 64
#define E_ 2
#define CIN_ 192
#define H0_ 128
#define OUT_ 64
#define NC 72          // 64 aggr cols + 1 ones col + 7 pad
#define EPS_ 1e-12f

// GEMM tiling
#define BM 128
#define BK 32
#define AS 40
#define BSW 20
#define STAGES 4
#define THREADS 256
#define KT (N_ / BK)

// MLP tiling
#define NT 64          // nodes per block
#define XS 200         // X smem row stride (floats)
#define HS 136         // H smem row stride (floats)
#define W0W (CIN_ / 2) // 96 words per w0 row
#define W1W (H0_ / 2)  // 64 words per w1 row

// Scratch (device globals; no allocation allowed)
__device__ __nv_bfloat16 g_BextB[T_ * NC * N_];  // [t][n(72)][k(4096)] bf16
__device__ float g_P[T_ * E_ * N_ * NC];         // GEMM results (row sums in col 64)
__device__ uint2 g_W0p[H0_ * W0W];               // (hi,lo) bf16x2 word pairs, [j][cword]
__device__ uint2 g_W1p[OUT_ * W1W];              // (hi,lo) word pairs, [o][hword]

__device__ __forceinline__ void cp16(void* dst_smem, const void* src_gmem) {
    unsigned d = (unsigned)__cvta_generic_to_shared(dst_smem);
    asm volatile("cp.async.cg.shared.global [%0], [%1], 16;\n" :: "r"(d), "l"(src_gmem));
}
__device__ __forceinline__ unsigned packbf(float lo, float hi) {
    unsigned r;
    asm("cvt.rn.bf16x2.f32 %0, %1, %2;" : "=r"(r) : "f"(hi), "f"(lo));
    return r;
}
// split fp32 pair into bf16x2 hi word + bf16x2 lo word
__device__ __forceinline__ void split2(float x, float y, unsigned& h, unsigned& l) {
    h = packbf(x, y);
    float hx = __uint_as_float(h << 16);
    float hy = __uint_as_float(h & 0xFFFF0000u);
    l = packbf(x - hx, y - hy);
}

#define MMA_BF16(ACC, A0, A1, A2, A3, B0, B1)                                  \
    asm volatile(                                                              \
        "mma.sync.aligned.m16n8k16.row.col.f32.bf16.bf16.f32 "                 \
        "{%0,%1,%2,%3}, {%4,%5,%6,%7}, {%8,%9}, {%0,%1,%2,%3};\n"              \
        : "+f"(ACC[0]), "+f"(ACC[1]), "+f"(ACC[2]), "+f"(ACC[3])               \
        : "r"(A0), "r"(A1), "r"(A2), "r"(A3), "r"(B0), "r"(B1))

// ---------------------------------------------------------------------------
// prep_b: transpose node -> g_BextB [t][n][k] bf16, ones row at n=64
// ---------------------------------------------------------------------------
__global__ void __launch_bounds__(256) prep_b_kernel(const float* __restrict__ node) {
    __shared__ float s[32][65];
    const int t = blockIdx.x >> 7;
    const int k0 = (blockIdx.x & 127) * 32;
    const int tid = threadIdx.x;
    for (int i = tid; i < 32 * 64; i += 256) {
        int r = i >> 6, d = i & 63;
        s[r][d] = node[((size_t)t * N_ + k0 + r) * D_ + d];
    }
    __syncthreads();
    for (int o = tid; o < NC * 32; o += 256) {
        int n = o >> 5, kk = o & 31;
        float v = (n < D_) ? s[kk][n] : (n == D_ ? 1.0f : 0.0f);
        g_BextB[((size_t)t * NC + n) * N_ + k0 + kk] = __float2bfloat16_rn(v);
    }
}

// ---------------------------------------------------------------------------
// prep_w: split weights into bf16 (hi,lo) word pairs
// ---------------------------------------------------------------------------
__global__ void prep_w_kernel(const float* __restrict__ w0,
                              const float* __restrict__ w1) {
    int i = blockIdx.x * 256 + threadIdx.x;
    if (i < H0_ * W0W) {
        int j = i / W0W, w = i % W0W;
        float v0 = w0[(size_t)j * CIN_ + 2 * w];
        float v1 = w0[(size_t)j * CIN_ + 2 * w + 1];
        unsigned h, l;
        split2(v0, v1, h, l);
        g_W0p[i] = make_uint2(h, l);
    }
    if (i < OUT_ * W1W) {
        int o = i / W1W, w = i % W1W;
        float v0 = w1[(size_t)o * H0_ + 2 * w];
        float v1 = w1[(size_t)o * H0_ + 2 * w + 1];
        unsigned h, l;
        split2(v0, v1, h, l);
        g_W1p[i] = make_uint2(h, l);
    }
}

// ---------------------------------------------------------------------------
// Main GEMM: P[t,e] = edge[t,e] (4096x4096) @ Bext[t] (4096x72), bf16 mma
// ---------------------------------------------------------------------------
__global__ void __launch_bounds__(256, 2) gemm_edge_kernel(const float* __restrict__ edge) {
    extern __shared__ unsigned smem[];
    float* sA = reinterpret_cast<float*>(smem);       // [STAGES][BM*AS]
    unsigned* sB = smem + STAGES * BM * AS;           // [STAGES][NC*BSW]

    const int te = blockIdx.y;
    const int t = te / E_;
    const int rowBase = blockIdx.x * BM;

    const float* __restrict__ Arow = edge + (size_t)te * N_ * N_ + (size_t)rowBase * N_;
    const __nv_bfloat16* __restrict__ Bbase = g_BextB + (size_t)t * NC * N_;

    const int tid = threadIdx.x;
    const int warp = tid >> 5;
    const int lane = tid & 31;
    const int g = lane >> 2;
    const int tq = lane & 3;

    const int arow = tid >> 3;
    const int acol = (tid & 7) * 4;

    float acc[9][4];
#pragma unroll
    for (int j = 0; j < 9; j++)
#pragma unroll
        for (int q = 0; q < 4; q++) acc[j][q] = 0.0f;

    auto load_stage = [&](int s, int k0) {
        float* dA = sA + s * (BM * AS);
        unsigned* dB = sB + s * (NC * BSW);
#pragma unroll
        for (int rr = 0; rr < BM; rr += 32) {
            cp16(&dA[(rr + arow) * AS + acol],
                 Arow + (size_t)(rr + arow) * N_ + k0 + acol);
        }
        for (int c = tid; c < NC * 4; c += THREADS) {
            int row = c >> 2, ch = c & 3;
            cp16(dB + row * BSW + ch * 4, Bbase + (size_t)row * N_ + k0 + ch * 8);
        }
    };

#pragma unroll
    for (int s = 0; s < STAGES - 1; s++) {
        load_stage(s, s * BK);
        asm volatile("cp.async.commit_group;\n");
    }

    for (int i = 0; i < KT; i++) {
        asm volatile("cp.async.wait_group %0;\n" :: "n"(STAGES - 2));
        __syncthreads();

        const int pf = i + STAGES - 1;
        if (pf < KT) load_stage(pf % STAGES, pf * BK);
        asm volatile("cp.async.commit_group;\n");

        const float* A = sA + (i % STAGES) * (BM * AS);
        const unsigned* B = sB + (i % STAGES) * (NC * BSW);
        const int r0 = warp * 16 + g;

#pragma unroll
        for (int ks = 0; ks < 2; ks++) {
            const int kb = ks * 16;
            float2 v;
            v = *reinterpret_cast<const float2*>(&A[r0 * AS + kb + 2 * tq]);
            const unsigned a0 = packbf(v.x, v.y);
            v = *reinterpret_cast<const float2*>(&A[(r0 + 8) * AS + kb + 2 * tq]);
            const unsigned a1 = packbf(v.x, v.y);
            v = *reinterpret_cast<const float2*>(&A[r0 * AS + kb + 2 * tq + 8]);
            const unsigned a2 = packbf(v.x, v.y);
            v = *reinterpret_cast<const float2*>(&A[(r0 + 8) * AS + kb + 2 * tq + 8]);
            const unsigned a3 = packbf(v.x, v.y);
#pragma unroll
            for (int j = 0; j < 9; j++) {
                const unsigned b0 = B[(j * 8 + g) * BSW + ks * 8 + tq];
                const unsigned b1 = B[(j * 8 + g) * BSW + ks * 8 + tq + 4];
                MMA_BF16(acc[j], a0, a1, a2, a3, b0, b1);
            }
        }
    }

    float* Pout = g_P + (size_t)te * N_ * NC;
    const int rg = rowBase + warp * 16 + g;
#pragma unroll
    for (int j = 0; j < 9; j++) {
        const int c = j * 8 + tq * 2;
        *reinterpret_cast<float2*>(Pout + (size_t)rg * NC + c) =
            make_float2(acc[j][0], acc[j][1]);
        *reinterpret_cast<float2*>(Pout + (size_t)(rg + 8) * NC + c) =
            make_float2(acc[j][2], acc[j][3]);
    }
}

// ---------------------------------------------------------------------------
// Fixup + MLP via split-bf16 tensor-core MMAs (fp32-equivalent precision).
// Block = 64 nodes, 256 threads (8 warps: 4 m-tiles x 2 n-halves).
// ---------------------------------------------------------------------------
__global__ void __launch_bounds__(256, 2) fixup_mlp_kernel(const float* __restrict__ node,
                                                           const float* __restrict__ edge,
                                                           float* __restrict__ out) {
    extern __shared__ float sm[];
    float* SX = sm;                       // NT * XS
    float* SH = SX + NT * XS;             // NT * HS
    float* sdiag = SH + NT * HS;          // E_ * NT
    float* sinv = sdiag + E_ * NT;        // E_ * NT

    const int tid = threadIdx.x;
    const int blk = blockIdx.x;
    const int t = blk / (N_ / NT);
    const int nbase = (blk % (N_ / NT)) * NT;

    if (tid < E_ * NT) {
        const int e = tid / NT, i = tid % NT;
        const int n = nbase + i;
        const size_t teN = ((size_t)(t * E_ + e)) * N_;
        const float dgf = edge[(teN + n) * N_ + n];
        const float dg = __bfloat162float(__float2bfloat16_rn(dgf));
        const float denom = g_P[(teN + n) * NC + D_] - dg;
        sdiag[tid] = dg;
        sinv[tid] = 1.0f / fmaxf(denom, EPS_);
    }
    __syncthreads();

    // build X = [node | aggr_e0 | aggr_e1], fp32
    for (int idx = tid; idx < NT * CIN_; idx += 256) {
        const int i = idx / CIN_, c = idx % CIN_;
        const int n = nbase + i;
        float v;
        if (c < D_) {
            v = node[((size_t)t * N_ + n) * D_ + c];
        } else {
            const int e = (c - D_) >> 6, d = (c - D_) & 63;
            const float nd = node[((size_t)t * N_ + n) * D_ + d];
            const float p = g_P[(((size_t)(t * E_ + e)) * N_ + n) * NC + d];
            v = (p - sdiag[e * NT + i] * nd) * sinv[e * NT + i];
        }
        SX[i * XS + c] = v;
    }
    __syncthreads();

    const int warp = tid >> 5;
    const int lane = tid & 31;
    const int g = lane >> 2;
    const int tq = lane & 3;
    const int wm = warp & 3;      // m-tile: rows wm*16..wm*16+15
    const int wn = warp >> 2;     // n-half

    // ---- layer 0: H = leaky(X @ W0^T), M=64, N=128 (64/warp-half), K=192 ----
    {
        float acc[8][4];
#pragma unroll
        for (int n = 0; n < 8; n++)
#pragma unroll
            for (int q = 0; q < 4; q++) acc[n][q] = 0.0f;

        const int r0 = wm * 16 + g;
#pragma unroll
        for (int kc = 0; kc < CIN_ / 16; kc++) {
            const int kb = kc * 16;
            const float* X0 = &SX[r0 * XS + kb];
            const float* X8 = X0 + 8 * XS;
            float2 v0 = *reinterpret_cast<const float2*>(X0 + 2 * tq);
            float2 v1 = *reinterpret_cast<const float2*>(X8 + 2 * tq);
            float2 v2 = *reinterpret_cast<const float2*>(X0 + 2 * tq + 8);
            float2 v3 = *reinterpret_cast<const float2*>(X8 + 2 * tq + 8);
            unsigned ah0, al0, ah1, al1, ah2, al2, ah3, al3;
            split2(v0.x, v0.y, ah0, al0);
            split2(v1.x, v1.y, ah1, al1);
            split2(v2.x, v2.y, ah2, al2);
            split2(v3.x, v3.y, ah3, al3);
#pragma unroll
            for (int n = 0; n < 8; n++) {
                const int row = wn * 64 + n * 8 + g;
                const uint2 b0 = g_W0p[row * W0W + kc * 8 + tq];
                const uint2 b1 = g_W0p[row * W0W + kc * 8 + tq + 4];
                MMA_BF16(acc[n], ah0, ah1, ah2, ah3, b0.x, b1.x);
                MMA_BF16(acc[n], ah0, ah1, ah2, ah3, b0.y, b1.y);
                MMA_BF16(acc[n], al0, al1, al2, al3, b0.x, b1.x);
            }
        }
        // leaky + store H
#pragma unroll
        for (int n = 0; n < 8; n++) {
            const int cb = wn * 64 + n * 8 + 2 * tq;
            float h0 = acc[n][0]; h0 = (h0 > 0.0f) ? h0 : 0.01f * h0;
            float h1 = acc[n][1]; h1 = (h1 > 0.0f) ? h1 : 0.01f * h1;
            float h2 = acc[n][2]; h2 = (h2 > 0.0f) ? h2 : 0.01f * h2;
            float h3 = acc[n][3]; h3 = (h3 > 0.0f) ? h3 : 0.01f * h3;
            *reinterpret_cast<float2*>(&SH[r0 * HS + cb]) = make_float2(h0, h1);
            *reinterpret_cast<float2*>(&SH[(r0 + 8) * HS + cb]) = make_float2(h2, h3);
        }
    }
    __syncthreads();

    // ---- layer 1: out = leaky(H @ W1^T), M=64, N=64 (32/warp-half), K=128 ----
    {
        float acc[4][4];
#pragma unroll
        for (int n = 0; n < 4; n++)
#pragma unroll
            for (int q = 0; q < 4; q++) acc[n][q] = 0.0f;

        const int r0 = wm * 16 + g;
#pragma unroll
        for (int kc = 0; kc < H0_ / 16; kc++) {
            const int kb = kc * 16;
            const float* Hh0 = &SH[r0 * HS + kb];
            const float* Hh8 = Hh0 + 8 * HS;
            float2 v0 = *reinterpret_cast<const float2*>(Hh0 + 2 * tq);
            float2 v1 = *reinterpret_cast<const float2*>(Hh8 + 2 * tq);
            float2 v2 = *reinterpret_cast<const float2*>(Hh0 + 2 * tq + 8);
            float2 v3 = *reinterpret_cast<const float2*>(Hh8 + 2 * tq + 8);
            unsigned ah0, al0, ah1, al1, ah2, al2, ah3, al3;
            split2(v0.x, v0.y, ah0, al0);
            split2(v1.x, v1.y, ah1, al1);
            split2(v2.x, v2.y, ah2, al2);
            split2(v3.x, v3.y, ah3, al3);
#pragma unroll
            for (int n = 0; n < 4; n++) {
                const int row = wn * 32 + n * 8 + g;
                const uint2 b0 = g_W1p[row * W1W + kc * 8 + tq];
                const uint2 b1 = g_W1p[row * W1W + kc * 8 + tq + 4];
                MMA_BF16(acc[n], ah0, ah1, ah2, ah3, b0.x, b1.x);
                MMA_BF16(acc[n], ah0, ah1, ah2, ah3, b0.y, b1.y);
                MMA_BF16(acc[n], al0, al1, al2, al3, b0.x, b1.x);
            }
        }
        // leaky + store out
        const int rglob = nbase + wm * 16 + g;
#pragma unroll
        for (int n = 0; n < 4; n++) {
            const int cb = wn * 32 + n * 8 + 2 * tq;
            float o0 = acc[n][0]; o0 = (o0 > 0.0f) ? o0 : 0.01f * o0;
            float o1 = acc[n][1]; o1 = (o1 > 0.0f) ? o1 : 0.01f * o1;
            float o2 = acc[n][2]; o2 = (o2 > 0.0f) ? o2 : 0.01f * o2;
            float o3 = acc[n][3]; o3 = (o3 > 0.0f) ? o3 : 0.01f * o3;
            *reinterpret_cast<float2*>(&out[((size_t)t * N_ + rglob) * OUT_ + cb]) =
                make_float2(o0, o1);
            *reinterpret_cast<float2*>(&out[((size_t)t * N_ + rglob + 8) * OUT_ + cb]) =
                make_float2(o2, o3);
        }
    }
}

// ---------------------------------------------------------------------------
extern "C" void kernel_launch(void* const* d_in, const int* in_sizes, int n_in,
                              void* d_out, int out_size) {
    const float* node = nullptr;
    const float* edge = nullptr;
    const float* w0 = nullptr;
    const float* w1 = nullptr;
    for (int i = 0; i < n_in; i++) {
        const int s = in_sizes[i];
        if (s == T_ * N_ * D_)            node = (const float*)d_in[i];
        else if (s == T_ * E_ * N_ * N_)  edge = (const float*)d_in[i];
        else if (s == H0_ * CIN_)         w0 = (const float*)d_in[i];
        else if (s == OUT_ * H0_)         w1 = (const float*)d_in[i];
    }

    prep_b_kernel<<<T_ * 128, 256>>>(node);
    prep_w_kernel<<<(H0_ * W0W + 255) / 256, 256>>>(w0, w1);

    {
        const size_t smem = (size_t)STAGES * (BM * AS + NC * BSW) * sizeof(unsigned);
        cudaFuncSetAttribute(gemm_edge_kernel,
                             cudaFuncAttributeMaxDynamicSharedMemorySize, (int)smem);
        dim3 grid(N_ / BM, T_ * E_);
        gemm_edge_kernel<<<grid, THREADS, smem>>>(edge);
    }
    {
        const size_t smem = (size_t)(NT * XS + NT * HS + 2 * E_ * NT) * sizeof(float);
        cudaFuncSetAttribute(fixup_mlp_kernel,
                             cudaFuncAttributeMaxDynamicSharedMemorySize, (int)smem);
        fixup_mlp_kernel<<<(T_ * N_) / NT, 256, smem>>>(node, edge, (float*)d_out);
    }
}

// round 8
// speedup vs baseline: 2.6577x; 1.1196x over previous
#include <cuda_runtime.h>
#include <cuda_bf16.h>
#include <cstdint>

// Problem constants
#define T_ 4
#define N_ 4096
#define D_ 64
#define E_ 2
#define CIN_ 192
#define H0_ 128
#define OUT_ 64
#define NC 72          // 64 aggr cols + 1 ones col + 7 pad
#define EPS_ 1e-12f

// GEMM tiling
#define BM 128
#define BK 32
#define AS 40
#define BSW 20
#define STAGES 4
#define THREADS 256
#define KT (N_ / BK)

// X layout: 96 words (bf16x2 hi/lo pairs) per node: [0,32)=node, [32,64)=e0, [64,96)=e1
#define XW 96
// MLP tiling
#define NT 64
#define SXS 100        // SXp row stride (uint2) — conflict-free per half-warp phase
#define SHS 68         // SHp row stride (uint2)
#define W0W 96
#define W1W 64

// Scratch (device globals; no allocation allowed)
__device__ __nv_bfloat16 g_BextB[T_ * NC * N_];  // [t][n(72)][k(4096)] bf16 (node^T + ones)
__device__ uint2 g_Xp[(size_t)T_ * N_ * XW];     // split-bf16 X, (hi,lo) word pairs
__device__ uint2 g_W0p[H0_ * W0W];               // (hi,lo) bf16x2 word pairs, [j][cword]
__device__ uint2 g_W1p[OUT_ * W1W];              // (hi,lo) word pairs, [o][hword]

__device__ __forceinline__ void cp16(void* dst_smem, const void* src_gmem) {
    unsigned d = (unsigned)__cvta_generic_to_shared(dst_smem);
    asm volatile("cp.async.cg.shared.global [%0], [%1], 16;\n" :: "r"(d), "l"(src_gmem));
}
__device__ __forceinline__ unsigned packbf(float lo, float hi) {
    unsigned r;
    asm("cvt.rn.bf16x2.f32 %0, %1, %2;" : "=r"(r) : "f"(hi), "f"(lo));
    return r;
}
__device__ __forceinline__ void split2(float x, float y, unsigned& h, unsigned& l) {
    h = packbf(x, y);
    float hx = __uint_as_float(h << 16);
    float hy = __uint_as_float(h & 0xFFFF0000u);
    l = packbf(x - hx, y - hy);
}

#define MMA_BF16(ACC, A0, A1, A2, A3, B0, B1)                                  \
    asm volatile(                                                              \
        "mma.sync.aligned.m16n8k16.row.col.f32.bf16.bf16.f32 "                 \
        "{%0,%1,%2,%3}, {%4,%5,%6,%7}, {%8,%9}, {%0,%1,%2,%3};\n"              \
        : "+f"(ACC[0]), "+f"(ACC[1]), "+f"(ACC[2]), "+f"(ACC[3])               \
        : "r"(A0), "r"(A1), "r"(A2), "r"(A3), "r"(B0), "r"(B1))

// ---------------------------------------------------------------------------
// prep_b: transpose node -> g_BextB bf16 (+ones row), and node part of g_Xp
// ---------------------------------------------------------------------------
__global__ void __launch_bounds__(256) prep_b_kernel(const float* __restrict__ node) {
    __shared__ float s[32][65];
    const int t = blockIdx.x >> 7;
    const int k0 = (blockIdx.x & 127) * 32;
    const int tid = threadIdx.x;
    for (int i = tid; i < 32 * 64; i += 256) {
        int r = i >> 6, d = i & 63;
        s[r][d] = node[((size_t)t * N_ + k0 + r) * D_ + d];
    }
    __syncthreads();
    // B^T for the GEMM
    for (int o = tid; o < NC * 32; o += 256) {
        int n = o >> 5, kk = o & 31;
        float v = (n < D_) ? s[kk][n] : (n == D_ ? 1.0f : 0.0f);
        g_BextB[((size_t)t * NC + n) * N_ + k0 + kk] = __float2bfloat16_rn(v);
    }
    // node part of split X (words 0..31)
    for (int o = tid; o < 32 * 32; o += 256) {
        int r = o >> 5, w = o & 31;
        unsigned h, l;
        split2(s[r][2 * w], s[r][2 * w + 1], h, l);
        g_Xp[((size_t)t * N_ + k0 + r) * XW + w] = make_uint2(h, l);
    }
}

// ---------------------------------------------------------------------------
// prep_w: split weights into bf16 (hi,lo) word pairs
// ---------------------------------------------------------------------------
__global__ void prep_w_kernel(const float* __restrict__ w0,
                              const float* __restrict__ w1) {
    int i = blockIdx.x * 256 + threadIdx.x;
    if (i < H0_ * W0W) {
        int j = i / W0W, w = i % W0W;
        unsigned h, l;
        split2(w0[(size_t)j * CIN_ + 2 * w], w0[(size_t)j * CIN_ + 2 * w + 1], h, l);
        g_W0p[i] = make_uint2(h, l);
    }
    if (i < OUT_ * W1W) {
        int o = i / W1W, w = i % W1W;
        unsigned h, l;
        split2(w1[(size_t)o * H0_ + 2 * w], w1[(size_t)o * H0_ + 2 * w + 1], h, l);
        g_W1p[i] = make_uint2(h, l);
    }
}

// ---------------------------------------------------------------------------
// Main GEMM + fused normalize epilogue: writes split-bf16 aggr directly to g_Xp
// ---------------------------------------------------------------------------
__global__ void __launch_bounds__(256, 2) gemm_edge_kernel(const float* __restrict__ edge,
                                                           const float* __restrict__ node) {
    extern __shared__ unsigned smem[];
    float* sA = reinterpret_cast<float*>(smem);       // [STAGES][BM*AS]
    unsigned* sB = smem + STAGES * BM * AS;           // [STAGES][NC*BSW]

    const int te = blockIdx.y;
    const int t = te / E_;
    const int e = te % E_;
    const int rowBase = blockIdx.x * BM;

    const float* __restrict__ Arow = edge + (size_t)te * N_ * N_ + (size_t)rowBase * N_;
    const __nv_bfloat16* __restrict__ Bbase = g_BextB + (size_t)t * NC * N_;

    const int tid = threadIdx.x;
    const int warp = tid >> 5;
    const int lane = tid & 31;
    const int g = lane >> 2;
    const int tq = lane & 3;

    const int arow = tid >> 3;
    const int acol = (tid & 7) * 4;

    float acc[9][4];
#pragma unroll
    for (int j = 0; j < 9; j++)
#pragma unroll
        for (int q = 0; q < 4; q++) acc[j][q] = 0.0f;

    auto load_stage = [&](int s, int k0) {
        float* dA = sA + s * (BM * AS);
        unsigned* dB = sB + s * (NC * BSW);
#pragma unroll
        for (int rr = 0; rr < BM; rr += 32) {
            cp16(&dA[(rr + arow) * AS + acol],
                 Arow + (size_t)(rr + arow) * N_ + k0 + acol);
        }
        for (int c = tid; c < NC * 4; c += THREADS) {
            int row = c >> 2, ch = c & 3;
            cp16(dB + row * BSW + ch * 4, Bbase + (size_t)row * N_ + k0 + ch * 8);
        }
    };

#pragma unroll
    for (int s = 0; s < STAGES - 1; s++) {
        load_stage(s, s * BK);
        asm volatile("cp.async.commit_group;\n");
    }

    for (int i = 0; i < KT; i++) {
        asm volatile("cp.async.wait_group %0;\n" :: "n"(STAGES - 2));
        __syncthreads();

        const int pf = i + STAGES - 1;
        if (pf < KT) load_stage(pf % STAGES, pf * BK);
        asm volatile("cp.async.commit_group;\n");

        const float* A = sA + (i % STAGES) * (BM * AS);
        const unsigned* B = sB + (i % STAGES) * (NC * BSW);
        const int r0 = warp * 16 + g;

#pragma unroll
        for (int ks = 0; ks < 2; ks++) {
            const int kb = ks * 16;
            float2 v;
            v = *reinterpret_cast<const float2*>(&A[r0 * AS + kb + 2 * tq]);
            const unsigned a0 = packbf(v.x, v.y);
            v = *reinterpret_cast<const float2*>(&A[(r0 + 8) * AS + kb + 2 * tq]);
            const unsigned a1 = packbf(v.x, v.y);
            v = *reinterpret_cast<const float2*>(&A[r0 * AS + kb + 2 * tq + 8]);
            const unsigned a2 = packbf(v.x, v.y);
            v = *reinterpret_cast<const float2*>(&A[(r0 + 8) * AS + kb + 2 * tq + 8]);
            const unsigned a3 = packbf(v.x, v.y);
#pragma unroll
            for (int j = 0; j < 9; j++) {
                const unsigned b0 = B[(j * 8 + g) * BSW + ks * 8 + tq];
                const unsigned b1 = B[(j * 8 + g) * BSW + ks * 8 + tq + 4];
                MMA_BF16(acc[j], a0, a1, a2, a3, b0, b1);
            }
        }
    }

    // ---- fused epilogue: normalize + split-bf16 store into g_Xp ----
    const int rg = rowBase + warp * 16 + g;
    // row sums live in the ones-column (col 64 = j=8, tq==0 lanes)
    const float rs0 = __shfl_sync(0xffffffffu, acc[8][0], lane & 28);
    const float rs1 = __shfl_sync(0xffffffffu, acc[8][2], lane & 28);
    const float dg0 = __bfloat162float(__float2bfloat16_rn(
        edge[(size_t)te * N_ * N_ + (size_t)rg * N_ + rg]));
    const float dg1 = __bfloat162float(__float2bfloat16_rn(
        edge[(size_t)te * N_ * N_ + (size_t)(rg + 8) * N_ + rg + 8]));
    const float inv0 = 1.0f / fmaxf(rs0 - dg0, EPS_);
    const float inv1 = 1.0f / fmaxf(rs1 - dg1, EPS_);
    const float* nrow0 = node + ((size_t)t * N_ + rg) * D_;
    const float* nrow1 = node + ((size_t)t * N_ + rg + 8) * D_;
    uint2* X0 = g_Xp + ((size_t)t * N_ + rg) * XW + 32 + 32 * e;
    uint2* X1 = g_Xp + ((size_t)t * N_ + rg + 8) * XW + 32 + 32 * e;
#pragma unroll
    for (int j = 0; j < 8; j++) {
        const int c = j * 8 + tq * 2;
        unsigned h, l;
        float2 nv0 = *reinterpret_cast<const float2*>(nrow0 + c);
        split2((acc[j][0] - dg0 * nv0.x) * inv0,
               (acc[j][1] - dg0 * nv0.y) * inv0, h, l);
        X0[j * 4 + tq] = make_uint2(h, l);
        float2 nv1 = *reinterpret_cast<const float2*>(nrow1 + c);
        split2((acc[j][2] - dg1 * nv1.x) * inv1,
               (acc[j][3] - dg1 * nv1.y) * inv1, h, l);
        X1[j * 4 + tq] = make_uint2(h, l);
    }
}

// ---------------------------------------------------------------------------
// MLP: X (pre-split in gmem) -> layer0 -> layer1, all tensor-core split-bf16.
// Block = 64 nodes, 256 threads (8 warps: 4 m-tiles x 2 n-halves).
// ---------------------------------------------------------------------------
__global__ void __launch_bounds__(256, 2) mlp_kernel(float* __restrict__ out) {
    extern __shared__ uint2 smu[];
    uint2* SXp = smu;                 // [NT][SXS]
    uint2* SHp = smu + NT * SXS;      // [NT][SHS]

    const int tid = threadIdx.x;
    const int blk = blockIdx.x;
    const int t = blk / (N_ / NT);
    const int nbase = (blk % (N_ / NT)) * NT;

    // stage split X rows (coalesced, 768B per node)
    {
        const uint2* src = g_Xp + ((size_t)t * N_ + nbase) * XW;
        for (int idx = tid; idx < NT * (XW / 2); idx += 256) {
            const int i = idx / (XW / 2), ch = idx % (XW / 2);
            cp16(&SXp[i * SXS + ch * 2], src + (size_t)i * XW + ch * 2);
        }
        asm volatile("cp.async.commit_group;\n");
        asm volatile("cp.async.wait_group 0;\n");
    }
    __syncthreads();

    const int warp = tid >> 5;
    const int lane = tid & 31;
    const int g = lane >> 2;
    const int tq = lane & 3;
    const int wm = warp & 3;
    const int wn = warp >> 2;
    const int r0 = wm * 16 + g;

    // ---- layer 0: H = leaky(X @ W0^T), K=192 (12 kc) ----
    {
        float acc[8][4];
#pragma unroll
        for (int n = 0; n < 8; n++)
#pragma unroll
            for (int q = 0; q < 4; q++) acc[n][q] = 0.0f;

#pragma unroll
        for (int kc = 0; kc < CIN_ / 16; kc++) {
            const uint2 a0 = SXp[r0 * SXS + kc * 8 + tq];
            const uint2 a1 = SXp[(r0 + 8) * SXS + kc * 8 + tq];
            const uint2 a2 = SXp[r0 * SXS + kc * 8 + tq + 4];
            const uint2 a3 = SXp[(r0 + 8) * SXS + kc * 8 + tq + 4];
#pragma unroll
            for (int n = 0; n < 8; n++) {
                const int row = wn * 64 + n * 8 + g;
                const uint2 b0 = g_W0p[row * W0W + kc * 8 + tq];
                const uint2 b1 = g_W0p[row * W0W + kc * 8 + tq + 4];
                MMA_BF16(acc[n], a0.x, a1.x, a2.x, a3.x, b0.x, b1.x);
                MMA_BF16(acc[n], a0.x, a1.x, a2.x, a3.x, b0.y, b1.y);
                MMA_BF16(acc[n], a0.y, a1.y, a2.y, a3.y, b0.x, b1.x);
            }
        }
        // leaky + split + store H
#pragma unroll
        for (int n = 0; n < 8; n++) {
            const int w = wn * 32 + n * 4 + tq;
            float h0 = acc[n][0]; h0 = (h0 > 0.0f) ? h0 : 0.01f * h0;
            float h1 = acc[n][1]; h1 = (h1 > 0.0f) ? h1 : 0.01f * h1;
            float h2 = acc[n][2]; h2 = (h2 > 0.0f) ? h2 : 0.01f * h2;
            float h3 = acc[n][3]; h3 = (h3 > 0.0f) ? h3 : 0.01f * h3;
            unsigned hh, ll;
            split2(h0, h1, hh, ll);
            SHp[r0 * SHS + w] = make_uint2(hh, ll);
            split2(h2, h3, hh, ll);
            SHp[(r0 + 8) * SHS + w] = make_uint2(hh, ll);
        }
    }
    __syncthreads();

    // ---- layer 1: out = leaky(H @ W1^T), K=128 (8 kc) ----
    {
        float acc[4][4];
#pragma unroll
        for (int n = 0; n < 4; n++)
#pragma unroll
            for (int q = 0; q < 4; q++) acc[n][q] = 0.0f;

#pragma unroll
        for (int kc = 0; kc < H0_ / 16; kc++) {
            const uint2 a0 = SHp[r0 * SHS + kc * 8 + tq];
            const uint2 a1 = SHp[(r0 + 8) * SHS + kc * 8 + tq];
            const uint2 a2 = SHp[r0 * SHS + kc * 8 + tq + 4];
            const uint2 a3 = SHp[(r0 + 8) * SHS + kc * 8 + tq + 4];
#pragma unroll
            for (int n = 0; n < 4; n++) {
                const int row = wn * 32 + n * 8 + g;
                const uint2 b0 = g_W1p[row * W1W + kc * 8 + tq];
                const uint2 b1 = g_W1p[row * W1W + kc * 8 + tq + 4];
                MMA_BF16(acc[n], a0.x, a1.x, a2.x, a3.x, b0.x, b1.x);
                MMA_BF16(acc[n], a0.x, a1.x, a2.x, a3.x, b0.y, b1.y);
                MMA_BF16(acc[n], a0.y, a1.y, a2.y, a3.y, b0.x, b1.x);
            }
        }
        const int rglob = nbase + r0;
#pragma unroll
        for (int n = 0; n < 4; n++) {
            const int cb = wn * 32 + n * 8 + 2 * tq;
            float o0 = acc[n][0]; o0 = (o0 > 0.0f) ? o0 : 0.01f * o0;
            float o1 = acc[n][1]; o1 = (o1 > 0.0f) ? o1 : 0.01f * o1;
            float o2 = acc[n][2]; o2 = (o2 > 0.0f) ? o2 : 0.01f * o2;
            float o3 = acc[n][3]; o3 = (o3 > 0.0f) ? o3 : 0.01f * o3;
            *reinterpret_cast<float2*>(&out[((size_t)t * N_ + rglob) * OUT_ + cb]) =
                make_float2(o0, o1);
            *reinterpret_cast<float2*>(&out[((size_t)t * N_ + rglob + 8) * OUT_ + cb]) =
                make_float2(o2, o3);
        }
    }
}

// ---------------------------------------------------------------------------
extern "C" void kernel_launch(void* const* d_in, const int* in_sizes, int n_in,
                              void* d_out, int out_size) {
    const float* node = nullptr;
    const float* edge = nullptr;
    const float* w0 = nullptr;
    const float* w1 = nullptr;
    for (int i = 0; i < n_in; i++) {
        const int s = in_sizes[i];
        if (s == T_ * N_ * D_)            node = (const float*)d_in[i];
        else if (s == T_ * E_ * N_ * N_)  edge = (const float*)d_in[i];
        else if (s == H0_ * CIN_)         w0 = (const float*)d_in[i];
        else if (s == OUT_ * H0_)         w1 = (const float*)d_in[i];
    }

    prep_b_kernel<<<T_ * 128, 256>>>(node);
    prep_w_kernel<<<(H0_ * W0W + 255) / 256, 256>>>(w0, w1);

    {
        const size_t smem = (size_t)STAGES * (BM * AS + NC * BSW) * sizeof(unsigned);
        cudaFuncSetAttribute(gemm_edge_kernel,
                             cudaFuncAttributeMaxDynamicSharedMemorySize, (int)smem);
        dim3 grid(N_ / BM, T_ * E_);
        gemm_edge_kernel<<<grid, THREADS, smem>>>(edge, node);
    }
    {
        const size_t smem = (size_t)(NT * SXS + NT * SHS) * sizeof(uint2);
        cudaFuncSetAttribute(mlp_kernel,
                             cudaFuncAttributeMaxDynamicSharedMemorySize, (int)smem);
        mlp_kernel<<<(T_ * N_) / NT, 256, smem>>>((float*)d_out);
    }
}

// round 9
// speedup vs baseline: 2.8095x; 1.0571x over previous
#include <cuda_runtime.h>
#include <cuda_bf16.h>
#include <cstdint>

// Problem constants
#define T_ 4
#define N_ 4096
#define D_ 64
#define E_ 2
#define CIN_ 192
#define H0_ 128
#define OUT_ 64
#define NC 72
#define EPS_ 1e-12f

// GEMM tiling: BM=112 -> 37x8 = 296 CTAs = exactly 2/SM on 148 SMs
#define BM 112
#define NWARP 7
#define GTHREADS (NWARP * 32)   // 224
#define BK 32
#define AS 40
#define BSW 20
#define STAGES 4
#define KT (N_ / BK)
#define GX 37                   // ceil(4096/112)

// X layout: 96 words (bf16x2 hi/lo pairs) per node
#define XW 96
// MLP tiling
#define NT 64
#define SXS 100
#define SHS 68
#define W0W 96
#define W1W 64

// Scratch (device globals; no allocation allowed)
__device__ __nv_bfloat16 g_BextB[T_ * NC * N_];
__device__ uint2 g_Xp[(size_t)T_ * N_ * XW];
__device__ uint2 g_W0p[H0_ * W0W];
__device__ uint2 g_W1p[OUT_ * W1W];

__device__ __forceinline__ void cp16(void* dst_smem, const void* src_gmem) {
    unsigned d = (unsigned)__cvta_generic_to_shared(dst_smem);
    asm volatile("cp.async.cg.shared.global [%0], [%1], 16;\n" :: "r"(d), "l"(src_gmem));
}
__device__ __forceinline__ unsigned packbf(float lo, float hi) {
    unsigned r;
    asm("cvt.rn.bf16x2.f32 %0, %1, %2;" : "=r"(r) : "f"(hi), "f"(lo));
    return r;
}
__device__ __forceinline__ void split2(float x, float y, unsigned& h, unsigned& l) {
    h = packbf(x, y);
    float hx = __uint_as_float(h << 16);
    float hy = __uint_as_float(h & 0xFFFF0000u);
    l = packbf(x - hx, y - hy);
}

#define MMA_BF16(ACC, A0, A1, A2, A3, B0, B1)                                  \
    asm volatile(                                                              \
        "mma.sync.aligned.m16n8k16.row.col.f32.bf16.bf16.f32 "                 \
        "{%0,%1,%2,%3}, {%4,%5,%6,%7}, {%8,%9}, {%0,%1,%2,%3};\n"              \
        : "+f"(ACC[0]), "+f"(ACC[1]), "+f"(ACC[2]), "+f"(ACC[3])               \
        : "r"(A0), "r"(A1), "r"(A2), "r"(A3), "r"(B0), "r"(B1))

// ---------------------------------------------------------------------------
// prep: blocks [0,512) transpose node -> g_BextB + node part of g_Xp;
//       blocks [512,560) split weights.
// ---------------------------------------------------------------------------
__global__ void __launch_bounds__(256) prep_kernel(const float* __restrict__ node,
                                                   const float* __restrict__ w0,
                                                   const float* __restrict__ w1) {
    const int tid = threadIdx.x;
    if (blockIdx.x >= 512) {
        int i = (blockIdx.x - 512) * 256 + tid;
        if (i < H0_ * W0W) {
            int j = i / W0W, w = i % W0W;
            unsigned h, l;
            split2(w0[(size_t)j * CIN_ + 2 * w], w0[(size_t)j * CIN_ + 2 * w + 1], h, l);
            g_W0p[i] = make_uint2(h, l);
        }
        if (i < OUT_ * W1W) {
            int o = i / W1W, w = i % W1W;
            unsigned h, l;
            split2(w1[(size_t)o * H0_ + 2 * w], w1[(size_t)o * H0_ + 2 * w + 1], h, l);
            g_W1p[i] = make_uint2(h, l);
        }
        return;
    }
    __shared__ float s[32][65];
    const int t = blockIdx.x >> 7;
    const int k0 = (blockIdx.x & 127) * 32;
    for (int i = tid; i < 32 * 64; i += 256) {
        int r = i >> 6, d = i & 63;
        s[r][d] = node[((size_t)t * N_ + k0 + r) * D_ + d];
    }
    __syncthreads();
    for (int o = tid; o < NC * 32; o += 256) {
        int n = o >> 5, kk = o & 31;
        float v = (n < D_) ? s[kk][n] : (n == D_ ? 1.0f : 0.0f);
        g_BextB[((size_t)t * NC + n) * N_ + k0 + kk] = __float2bfloat16_rn(v);
    }
    for (int o = tid; o < 32 * 32; o += 256) {
        int r = o >> 5, w = o & 31;
        unsigned h, l;
        split2(s[r][2 * w], s[r][2 * w + 1], h, l);
        g_Xp[((size_t)t * N_ + k0 + r) * XW + w] = make_uint2(h, l);
    }
}

// ---------------------------------------------------------------------------
// Main GEMM + fused normalize epilogue -> split-bf16 g_Xp.
// BM=112, 224 threads (7 warps x 16 rows), 296 CTAs = 2/SM exactly.
// ---------------------------------------------------------------------------
__global__ void __launch_bounds__(GTHREADS, 2) gemm_edge_kernel(const float* __restrict__ edge,
                                                                const float* __restrict__ node) {
    extern __shared__ unsigned smem[];
    float* sA = reinterpret_cast<float*>(smem);       // [STAGES][BM*AS]
    unsigned* sB = smem + STAGES * BM * AS;           // [STAGES][NC*BSW]

    const int te = blockIdx.y;
    const int t = te / E_;
    const int e = te % E_;
    const int rowBase = blockIdx.x * BM;

    const float* __restrict__ Abase = edge + (size_t)te * N_ * N_;
    const __nv_bfloat16* __restrict__ Bbase = g_BextB + (size_t)t * NC * N_;

    const int tid = threadIdx.x;
    const int warp = tid >> 5;
    const int lane = tid & 31;
    const int g = lane >> 2;
    const int tq = lane & 3;

    const int arow = tid >> 3;          // 0..27
    const int acol = (tid & 7) * 4;

    float acc[9][4];
#pragma unroll
    for (int j = 0; j < 9; j++)
#pragma unroll
        for (int q = 0; q < 4; q++) acc[j][q] = 0.0f;

    auto load_stage = [&](int s, int k0) {
        float* dA = sA + s * (BM * AS);
        unsigned* dB = sB + s * (NC * BSW);
#pragma unroll
        for (int rr = 0; rr < BM; rr += 28) {
            int row = rowBase + rr + arow;
            if (row >= N_) row = N_ - 1;              // clamp (L2-hit, last tile only)
            cp16(&dA[(rr + arow) * AS + acol],
                 Abase + (size_t)row * N_ + k0 + acol);
        }
        for (int c = tid; c < NC * 4; c += GTHREADS) {
            int row = c >> 2, ch = c & 3;
            cp16(dB + row * BSW + ch * 4, Bbase + (size_t)row * N_ + k0 + ch * 8);
        }
    };

#pragma unroll
    for (int s = 0; s < STAGES - 1; s++) {
        load_stage(s, s * BK);
        asm volatile("cp.async.commit_group;\n");
    }

    for (int i = 0; i < KT; i++) {
        asm volatile("cp.async.wait_group %0;\n" :: "n"(STAGES - 2));
        __syncthreads();

        const int pf = i + STAGES - 1;
        if (pf < KT) load_stage(pf % STAGES, pf * BK);
        asm volatile("cp.async.commit_group;\n");

        const float* A = sA + (i % STAGES) * (BM * AS);
        const unsigned* B = sB + (i % STAGES) * (NC * BSW);
        const int r0 = warp * 16 + g;

#pragma unroll
        for (int ks = 0; ks < 2; ks++) {
            const int kb = ks * 16;
            float2 v;
            v = *reinterpret_cast<const float2*>(&A[r0 * AS + kb + 2 * tq]);
            const unsigned a0 = packbf(v.x, v.y);
            v = *reinterpret_cast<const float2*>(&A[(r0 + 8) * AS + kb + 2 * tq]);
            const unsigned a1 = packbf(v.x, v.y);
            v = *reinterpret_cast<const float2*>(&A[r0 * AS + kb + 2 * tq + 8]);
            const unsigned a2 = packbf(v.x, v.y);
            v = *reinterpret_cast<const float2*>(&A[(r0 + 8) * AS + kb + 2 * tq + 8]);
            const unsigned a3 = packbf(v.x, v.y);
#pragma unroll
            for (int j = 0; j < 9; j++) {
                const unsigned b0 = B[(j * 8 + g) * BSW + ks * 8 + tq];
                const unsigned b1 = B[(j * 8 + g) * BSW + ks * 8 + tq + 4];
                MMA_BF16(acc[j], a0, a1, a2, a3, b0, b1);
            }
        }
    }

    // ---- fused epilogue: normalize + split-bf16 store into g_Xp ----
    const int rg = rowBase + warp * 16 + g;
    const bool rv0 = (rg < N_);
    const bool rv1 = (rg + 8 < N_);
    const float rs0 = __shfl_sync(0xffffffffu, acc[8][0], lane & 28);
    const float rs1 = __shfl_sync(0xffffffffu, acc[8][2], lane & 28);
    float dg0 = 0.0f, dg1 = 0.0f;
    if (rv0) dg0 = __bfloat162float(__float2bfloat16_rn(
        Abase[(size_t)rg * N_ + rg]));
    if (rv1) dg1 = __bfloat162float(__float2bfloat16_rn(
        Abase[(size_t)(rg + 8) * N_ + rg + 8]));
    const float inv0 = 1.0f / fmaxf(rs0 - dg0, EPS_);
    const float inv1 = 1.0f / fmaxf(rs1 - dg1, EPS_);
    const float* nrow0 = node + ((size_t)t * N_ + (rv0 ? rg : 0)) * D_;
    const float* nrow1 = node + ((size_t)t * N_ + (rv1 ? rg + 8 : 0)) * D_;
    uint2* X0 = g_Xp + ((size_t)t * N_ + (rv0 ? rg : 0)) * XW + 32 + 32 * e;
    uint2* X1 = g_Xp + ((size_t)t * N_ + (rv1 ? rg + 8 : 0)) * XW + 32 + 32 * e;
#pragma unroll
    for (int j = 0; j < 8; j++) {
        const int c = j * 8 + tq * 2;
        unsigned h, l;
        if (rv0) {
            float2 nv0 = *reinterpret_cast<const float2*>(nrow0 + c);
            split2((acc[j][0] - dg0 * nv0.x) * inv0,
                   (acc[j][1] - dg0 * nv0.y) * inv0, h, l);
            X0[j * 4 + tq] = make_uint2(h, l);
        }
        if (rv1) {
            float2 nv1 = *reinterpret_cast<const float2*>(nrow1 + c);
            split2((acc[j][2] - dg1 * nv1.x) * inv1,
                   (acc[j][3] - dg1 * nv1.y) * inv1, h, l);
            X1[j * 4 + tq] = make_uint2(h, l);
        }
    }
}

// ---------------------------------------------------------------------------
// MLP: X (pre-split in gmem) -> layer0 -> layer1, split-bf16 tensor core.
// ---------------------------------------------------------------------------
__global__ void __launch_bounds__(256, 2) mlp_kernel(float* __restrict__ out) {
    extern __shared__ uint2 smu[];
    uint2* SXp = smu;                 // [NT][SXS]
    uint2* SHp = smu + NT * SXS;      // [NT][SHS]

    const int tid = threadIdx.x;
    const int blk = blockIdx.x;
    const int t = blk / (N_ / NT);
    const int nbase = (blk % (N_ / NT)) * NT;

    {
        const uint2* src = g_Xp + ((size_t)t * N_ + nbase) * XW;
        for (int idx = tid; idx < NT * (XW / 2); idx += 256) {
            const int i = idx / (XW / 2), ch = idx % (XW / 2);
            cp16(&SXp[i * SXS + ch * 2], src + (size_t)i * XW + ch * 2);
        }
        asm volatile("cp.async.commit_group;\n");
        asm volatile("cp.async.wait_group 0;\n");
    }
    __syncthreads();

    const int warp = tid >> 5;
    const int lane = tid & 31;
    const int g = lane >> 2;
    const int tq = lane & 3;
    const int wm = warp & 3;
    const int wn = warp >> 2;
    const int r0 = wm * 16 + g;

    // layer 0
    {
        float acc[8][4];
#pragma unroll
        for (int n = 0; n < 8; n++)
#pragma unroll
            for (int q = 0; q < 4; q++) acc[n][q] = 0.0f;

#pragma unroll
        for (int kc = 0; kc < CIN_ / 16; kc++) {
            const uint2 a0 = SXp[r0 * SXS + kc * 8 + tq];
            const uint2 a1 = SXp[(r0 + 8) * SXS + kc * 8 + tq];
            const uint2 a2 = SXp[r0 * SXS + kc * 8 + tq + 4];
            const uint2 a3 = SXp[(r0 + 8) * SXS + kc * 8 + tq + 4];
#pragma unroll
            for (int n = 0; n < 8; n++) {
                const int row = wn * 64 + n * 8 + g;
                const uint2 b0 = g_W0p[row * W0W + kc * 8 + tq];
                const uint2 b1 = g_W0p[row * W0W + kc * 8 + tq + 4];
                MMA_BF16(acc[n], a0.x, a1.x, a2.x, a3.x, b0.x, b1.x);
                MMA_BF16(acc[n], a0.x, a1.x, a2.x, a3.x, b0.y, b1.y);
                MMA_BF16(acc[n], a0.y, a1.y, a2.y, a3.y, b0.x, b1.x);
            }
        }
#pragma unroll
        for (int n = 0; n < 8; n++) {
            const int w = wn * 32 + n * 4 + tq;
            float h0 = acc[n][0]; h0 = (h0 > 0.0f) ? h0 : 0.01f * h0;
            float h1 = acc[n][1]; h1 = (h1 > 0.0f) ? h1 : 0.01f * h1;
            float h2 = acc[n][2]; h2 = (h2 > 0.0f) ? h2 : 0.01f * h2;
            float h3 = acc[n][3]; h3 = (h3 > 0.0f) ? h3 : 0.01f * h3;
            unsigned hh, ll;
            split2(h0, h1, hh, ll);
            SHp[r0 * SHS + w] = make_uint2(hh, ll);
            split2(h2, h3, hh, ll);
            SHp[(r0 + 8) * SHS + w] = make_uint2(hh, ll);
        }
    }
    __syncthreads();

    // layer 1
    {
        float acc[4][4];
#pragma unroll
        for (int n = 0; n < 4; n++)
#pragma unroll
            for (int q = 0; q < 4; q++) acc[n][q] = 0.0f;

#pragma unroll
        for (int kc = 0; kc < H0_ / 16; kc++) {
            const uint2 a0 = SHp[r0 * SHS + kc * 8 + tq];
            const uint2 a1 = SHp[(r0 + 8) * SHS + kc * 8 + tq];
            const uint2 a2 = SHp[r0 * SHS + kc * 8 + tq + 4];
            const uint2 a3 = SHp[(r0 + 8) * SHS + kc * 8 + tq + 4];
#pragma unroll
            for (int n = 0; n < 4; n++) {
                const int row = wn * 32 + n * 8 + g;
                const uint2 b0 = g_W1p[row * W1W + kc * 8 + tq];
                const uint2 b1 = g_W1p[row * W1W + kc * 8 + tq + 4];
                MMA_BF16(acc[n], a0.x, a1.x, a2.x, a3.x, b0.x, b1.x);
                MMA_BF16(acc[n], a0.x, a1.x, a2.x, a3.x, b0.y, b1.y);
                MMA_BF16(acc[n], a0.y, a1.y, a2.y, a3.y, b0.x, b1.x);
            }
        }
        const int rglob = nbase + r0;
#pragma unroll
        for (int n = 0; n < 4; n++) {
            const int cb = wn * 32 + n * 8 + 2 * tq;
            float o0 = acc[n][0]; o0 = (o0 > 0.0f) ? o0 : 0.01f * o0;
            float o1 = acc[n][1]; o1 = (o1 > 0.0f) ? o1 : 0.01f * o1;
            float o2 = acc[n][2]; o2 = (o2 > 0.0f) ? o2 : 0.01f * o2;
            float o3 = acc[n][3]; o3 = (o3 > 0.0f) ? o3 : 0.01f * o3;
            *reinterpret_cast<float2*>(&out[((size_t)t * N_ + rglob) * OUT_ + cb]) =
                make_float2(o0, o1);
            *reinterpret_cast<float2*>(&out[((size_t)t * N_ + rglob + 8) * OUT_ + cb]) =
                make_float2(o2, o3);
        }
    }
}

// ---------------------------------------------------------------------------
extern "C" void kernel_launch(void* const* d_in, const int* in_sizes, int n_in,
                              void* d_out, int out_size) {
    const float* node = nullptr;
    const float* edge = nullptr;
    const float* w0 = nullptr;
    const float* w1 = nullptr;
    for (int i = 0; i < n_in; i++) {
        const int s = in_sizes[i];
        if (s == T_ * N_ * D_)            node = (const float*)d_in[i];
        else if (s == T_ * E_ * N_ * N_)  edge = (const float*)d_in[i];
        else if (s == H0_ * CIN_)         w0 = (const float*)d_in[i];
        else if (s == OUT_ * H0_)         w1 = (const float*)d_in[i];
    }

    prep_kernel<<<512 + 48, 256>>>(node, w0, w1);

    {
        const size_t smem = (size_t)STAGES * (BM * AS + NC * BSW) * sizeof(unsigned);
        cudaFuncSetAttribute(gemm_edge_kernel,
                             cudaFuncAttributeMaxDynamicSharedMemorySize, (int)smem);
        dim3 grid(GX, T_ * E_);
        gemm_edge_kernel<<<grid, GTHREADS, smem>>>(edge, node);
    }
    {
        const size_t smem = (size_t)(NT * SXS + NT * SHS) * sizeof(uint2);
        cudaFuncSetAttribute(mlp_kernel,
                             cudaFuncAttributeMaxDynamicSharedMemorySize, (int)smem);
        mlp_kernel<<<(T_ * N_) / NT, 256, smem>>>((float*)d_out);
    }
}

// round 10
// speedup vs baseline: 2.8554x; 1.0163x over previous
#include <cuda_runtime.h>
#include <cuda_bf16.h>
#include <cstdint>

// Problem constants
#define T_ 4
#define N_ 4096
#define D_ 64
#define E_ 2
#define CIN_ 192
#define H0_ 128
#define OUT_ 64
#define NC 72
#define EPS_ 1e-12f

// GEMM tiling: BM=112 -> 37x8 = 296 CTAs = exactly 2/SM on 148 SMs
#define BM 112
#define NWARP 7
#define GTHREADS (NWARP * 32)   // 224
#define BK 32
#define AS 40
#define BSW 16                  // B smem row stride in words (k-permuted layout)
#define STAGES 5
#define KT (N_ / BK)
#define GX 37

// X layout: 96 words (bf16x2 hi/lo pairs) per node
#define XW 96
// MLP tiling
#define NT 64
#define SHS 68
#define W0W 96
#define W1W 64

// Scratch (device globals; no allocation allowed)
__device__ __nv_bfloat16 g_BextB[T_ * NC * N_];  // k-permuted within 32-groups
__device__ uint2 g_Xp[(size_t)T_ * N_ * XW];
__device__ uint2 g_W0p[H0_ * W0W];
__device__ uint2 g_W1p[OUT_ * W1W];

__device__ __forceinline__ void cp16(void* dst_smem, const void* src_gmem) {
    unsigned d = (unsigned)__cvta_generic_to_shared(dst_smem);
    asm volatile("cp.async.cg.shared.global [%0], [%1], 16;\n" :: "r"(d), "l"(src_gmem));
}
__device__ __forceinline__ unsigned packbf(float lo, float hi) {
    unsigned r;
    asm("cvt.rn.bf16x2.f32 %0, %1, %2;" : "=r"(r) : "f"(hi), "f"(lo));
    return r;
}
__device__ __forceinline__ void split2(float x, float y, unsigned& h, unsigned& l) {
    h = packbf(x, y);
    float hx = __uint_as_float(h << 16);
    float hy = __uint_as_float(h & 0xFFFF0000u);
    l = packbf(x - hx, y - hy);
}

#define MMA_BF16(ACC, A0, A1, A2, A3, B0, B1)                                  \
    asm volatile(                                                              \
        "mma.sync.aligned.m16n8k16.row.col.f32.bf16.bf16.f32 "                 \
        "{%0,%1,%2,%3}, {%4,%5,%6,%7}, {%8,%9}, {%0,%1,%2,%3};\n"              \
        : "+f"(ACC[0]), "+f"(ACC[1]), "+f"(ACC[2]), "+f"(ACC[3])               \
        : "r"(A0), "r"(A1), "r"(A2), "r"(A3), "r"(B0), "r"(B1))

// ---------------------------------------------------------------------------
// prep: blocks [0,512): node -> g_BextB (k-permuted) + node part of g_Xp;
//       blocks [512,560): split weights.
// k-permutation within each 32-group: word w_orig -> w_new = 4*(w_orig%4)+(w_orig/4)
// so a single LDS.128 in the GEMM yields {b0_ks0, b1_ks0, b0_ks1, b1_ks1}.
// ---------------------------------------------------------------------------
__global__ void __launch_bounds__(256) prep_kernel(const float* __restrict__ node,
                                                   const float* __restrict__ w0,
                                                   const float* __restrict__ w1) {
    const int tid = threadIdx.x;
    if (blockIdx.x >= 512) {
        int i = (blockIdx.x - 512) * 256 + tid;
        if (i < H0_ * W0W) {
            int j = i / W0W, w = i % W0W;
            unsigned h, l;
            split2(w0[(size_t)j * CIN_ + 2 * w], w0[(size_t)j * CIN_ + 2 * w + 1], h, l);
            g_W0p[i] = make_uint2(h, l);
        }
        if (i < OUT_ * W1W) {
            int o = i / W1W, w = i % W1W;
            unsigned h, l;
            split2(w1[(size_t)o * H0_ + 2 * w], w1[(size_t)o * H0_ + 2 * w + 1], h, l);
            g_W1p[i] = make_uint2(h, l);
        }
        return;
    }
    __shared__ float s[32][65];
    const int t = blockIdx.x >> 7;
    const int k0 = (blockIdx.x & 127) * 32;
    for (int i = tid; i < 32 * 64; i += 256) {
        int r = i >> 6, d = i & 63;
        s[r][d] = node[((size_t)t * N_ + k0 + r) * D_ + d];
    }
    __syncthreads();
    for (int o = tid; o < NC * 32; o += 256) {
        int n = o >> 5, kk = o & 31;
        float v = (n < D_) ? s[kk][n] : (n == D_ ? 1.0f : 0.0f);
        const int worig = kk >> 1, b = kk & 1;
        const int kpos = 2 * (4 * (worig & 3) + (worig >> 2)) + b;
        g_BextB[((size_t)t * NC + n) * N_ + k0 + kpos] = __float2bfloat16_rn(v);
    }
    for (int o = tid; o < 32 * 32; o += 256) {
        int r = o >> 5, w = o & 31;
        unsigned h, l;
        split2(s[r][2 * w], s[r][2 * w + 1], h, l);
        g_Xp[((size_t)t * N_ + k0 + r) * XW + w] = make_uint2(h, l);
    }
}

// ---------------------------------------------------------------------------
// Main GEMM + fused normalize epilogue -> split-bf16 g_Xp.
// BM=112, 224 threads, 296 CTAs = 2/SM; 5-stage cp.async; B via LDS.128.
// ---------------------------------------------------------------------------
__global__ void __launch_bounds__(GTHREADS, 2) gemm_edge_kernel(const float* __restrict__ edge,
                                                                const float* __restrict__ node) {
    extern __shared__ unsigned smem[];
    float* sA = reinterpret_cast<float*>(smem);       // [STAGES][BM*AS]
    unsigned* sB = smem + STAGES * BM * AS;           // [STAGES][NC*BSW]

    const int te = blockIdx.y;
    const int t = te / E_;
    const int e = te % E_;
    const int rowBase = blockIdx.x * BM;

    const float* __restrict__ Abase = edge + (size_t)te * N_ * N_;
    const __nv_bfloat16* __restrict__ Bbase = g_BextB + (size_t)t * NC * N_;

    const int tid = threadIdx.x;
    const int warp = tid >> 5;
    const int lane = tid & 31;
    const int g = lane >> 2;
    const int tq = lane & 3;

    const int arow = tid >> 3;          // 0..27
    const int acol = (tid & 7) * 4;

    float acc[9][4];
#pragma unroll
    for (int j = 0; j < 9; j++)
#pragma unroll
        for (int q = 0; q < 4; q++) acc[j][q] = 0.0f;

    auto load_stage = [&](int s, int k0) {
        float* dA = sA + s * (BM * AS);
        unsigned* dB = sB + s * (NC * BSW);
#pragma unroll
        for (int rr = 0; rr < BM; rr += 28) {
            int row = rowBase + rr + arow;
            if (row >= N_) row = N_ - 1;
            cp16(&dA[(rr + arow) * AS + acol],
                 Abase + (size_t)row * N_ + k0 + acol);
        }
        // B: 72 rows x 64B = 288 16B-chunks
        for (int c = tid; c < NC * 4; c += GTHREADS) {
            int row = c >> 2, ch = c & 3;
            cp16(dB + row * BSW + ch * 4, Bbase + (size_t)row * N_ + k0 + ch * 8);
        }
    };

#pragma unroll
    for (int s = 0; s < STAGES - 1; s++) {
        load_stage(s, s * BK);
        asm volatile("cp.async.commit_group;\n");
    }

    for (int i = 0; i < KT; i++) {
        asm volatile("cp.async.wait_group %0;\n" :: "n"(STAGES - 2));
        __syncthreads();

        const int pf = i + STAGES - 1;
        if (pf < KT) load_stage(pf % STAGES, pf * BK);
        asm volatile("cp.async.commit_group;\n");

        const float* A = sA + (i % STAGES) * (BM * AS);
        const uint4* B4 = reinterpret_cast<const uint4*>(sB + (i % STAGES) * (NC * BSW));
        const int r0 = warp * 16 + g;

        unsigned a[2][4];
#pragma unroll
        for (int ks = 0; ks < 2; ks++) {
            const int kb = ks * 16;
            float2 v;
            v = *reinterpret_cast<const float2*>(&A[r0 * AS + kb + 2 * tq]);
            a[ks][0] = packbf(v.x, v.y);
            v = *reinterpret_cast<const float2*>(&A[(r0 + 8) * AS + kb + 2 * tq]);
            a[ks][1] = packbf(v.x, v.y);
            v = *reinterpret_cast<const float2*>(&A[r0 * AS + kb + 2 * tq + 8]);
            a[ks][2] = packbf(v.x, v.y);
            v = *reinterpret_cast<const float2*>(&A[(r0 + 8) * AS + kb + 2 * tq + 8]);
            a[ks][3] = packbf(v.x, v.y);
        }
#pragma unroll
        for (int j = 0; j < 9; j++) {
            const uint4 bq = B4[(j * 8 + g) * 4 + tq];   // {b0_ks0,b1_ks0,b0_ks1,b1_ks1}
            MMA_BF16(acc[j], a[0][0], a[0][1], a[0][2], a[0][3], bq.x, bq.y);
            MMA_BF16(acc[j], a[1][0], a[1][1], a[1][2], a[1][3], bq.z, bq.w);
        }
    }

    // ---- fused epilogue: normalize + split-bf16 store into g_Xp ----
    const int rg = rowBase + warp * 16 + g;
    const bool rv0 = (rg < N_);
    const bool rv1 = (rg + 8 < N_);
    const float rs0 = __shfl_sync(0xffffffffu, acc[8][0], lane & 28);
    const float rs1 = __shfl_sync(0xffffffffu, acc[8][2], lane & 28);
    float dg0 = 0.0f, dg1 = 0.0f;
    if (rv0) dg0 = __bfloat162float(__float2bfloat16_rn(Abase[(size_t)rg * N_ + rg]));
    if (rv1) dg1 = __bfloat162float(__float2bfloat16_rn(Abase[(size_t)(rg + 8) * N_ + rg + 8]));
    const float inv0 = 1.0f / fmaxf(rs0 - dg0, EPS_);
    const float inv1 = 1.0f / fmaxf(rs1 - dg1, EPS_);
    const float* nrow0 = node + ((size_t)t * N_ + (rv0 ? rg : 0)) * D_;
    const float* nrow1 = node + ((size_t)t * N_ + (rv1 ? rg + 8 : 0)) * D_;
    uint2* X0 = g_Xp + ((size_t)t * N_ + (rv0 ? rg : 0)) * XW + 32 + 32 * e;
    uint2* X1 = g_Xp + ((size_t)t * N_ + (rv1 ? rg + 8 : 0)) * XW + 32 + 32 * e;
#pragma unroll
    for (int j = 0; j < 8; j++) {
        const int c = j * 8 + tq * 2;
        unsigned h, l;
        if (rv0) {
            float2 nv0 = *reinterpret_cast<const float2*>(nrow0 + c);
            split2((acc[j][0] - dg0 * nv0.x) * inv0,
                   (acc[j][1] - dg0 * nv0.y) * inv0, h, l);
            X0[j * 4 + tq] = make_uint2(h, l);
        }
        if (rv1) {
            float2 nv1 = *reinterpret_cast<const float2*>(nrow1 + c);
            split2((acc[j][2] - dg1 * nv1.x) * inv1,
                   (acc[j][3] - dg1 * nv1.y) * inv1, h, l);
            X1[j * 4 + tq] = make_uint2(h, l);
        }
    }
}

// ---------------------------------------------------------------------------
// MLP: X fragments streamed from gmem (__ldcs, evict-first) so the 131KB
// weight set stays L1-resident; only H staged in smem (35KB/CTA).
// ---------------------------------------------------------------------------
__global__ void __launch_bounds__(256, 2) mlp_kernel(float* __restrict__ out) {
    extern __shared__ uint2 smu[];
    uint2* SHp = smu;                 // [NT][SHS]

    const int tid = threadIdx.x;
    const int blk = blockIdx.x;
    const int t = blk / (N_ / NT);
    const int nbase = (blk % (N_ / NT)) * NT;

    const int warp = tid >> 5;
    const int lane = tid & 31;
    const int g = lane >> 2;
    const int tq = lane & 3;
    const int wm = warp & 3;
    const int wn = warp >> 2;
    const int r0 = wm * 16 + g;

    // layer 0: A fragments direct from gmem
    {
        float acc[8][4];
#pragma unroll
        for (int n = 0; n < 8; n++)
#pragma unroll
            for (int q = 0; q < 4; q++) acc[n][q] = 0.0f;

        const uint2* Xr0 = g_Xp + ((size_t)t * N_ + nbase + r0) * XW;
        const uint2* Xr1 = Xr0 + 8 * XW;
#pragma unroll
        for (int kc = 0; kc < CIN_ / 16; kc++) {
            const uint2 a0 = __ldcs(&Xr0[kc * 8 + tq]);
            const uint2 a1 = __ldcs(&Xr1[kc * 8 + tq]);
            const uint2 a2 = __ldcs(&Xr0[kc * 8 + tq + 4]);
            const uint2 a3 = __ldcs(&Xr1[kc * 8 + tq + 4]);
#pragma unroll
            for (int n = 0; n < 8; n++) {
                const int row = wn * 64 + n * 8 + g;
                const uint2 b0 = g_W0p[row * W0W + kc * 8 + tq];
                const uint2 b1 = g_W0p[row * W0W + kc * 8 + tq + 4];
                MMA_BF16(acc[n], a0.x, a1.x, a2.x, a3.x, b0.x, b1.x);
                MMA_BF16(acc[n], a0.x, a1.x, a2.x, a3.x, b0.y, b1.y);
                MMA_BF16(acc[n], a0.y, a1.y, a2.y, a3.y, b0.x, b1.x);
            }
        }
#pragma unroll
        for (int n = 0; n < 8; n++) {
            const int w = wn * 32 + n * 4 + tq;
            float h0 = acc[n][0]; h0 = (h0 > 0.0f) ? h0 : 0.01f * h0;
            float h1 = acc[n][1]; h1 = (h1 > 0.0f) ? h1 : 0.01f * h1;
            float h2 = acc[n][2]; h2 = (h2 > 0.0f) ? h2 : 0.01f * h2;
            float h3 = acc[n][3]; h3 = (h3 > 0.0f) ? h3 : 0.01f * h3;
            unsigned hh, ll;
            split2(h0, h1, hh, ll);
            SHp[r0 * SHS + w] = make_uint2(hh, ll);
            split2(h2, h3, hh, ll);
            SHp[(r0 + 8) * SHS + w] = make_uint2(hh, ll);
        }
    }
    __syncthreads();

    // layer 1
    {
        float acc[4][4];
#pragma unroll
        for (int n = 0; n < 4; n++)
#pragma unroll
            for (int q = 0; q < 4; q++) acc[n][q] = 0.0f;

#pragma unroll
        for (int kc = 0; kc < H0_ / 16; kc++) {
            const uint2 a0 = SHp[r0 * SHS + kc * 8 + tq];
            const uint2 a1 = SHp[(r0 + 8) * SHS + kc * 8 + tq];
            const uint2 a2 = SHp[r0 * SHS + kc * 8 + tq + 4];
            const uint2 a3 = SHp[(r0 + 8) * SHS + kc * 8 + tq + 4];
#pragma unroll
            for (int n = 0; n < 4; n++) {
                const int row = wn * 32 + n * 8 + g;
                const uint2 b0 = g_W1p[row * W1W + kc * 8 + tq];
                const uint2 b1 = g_W1p[row * W1W + kc * 8 + tq + 4];
                MMA_BF16(acc[n], a0.x, a1.x, a2.x, a3.x, b0.x, b1.x);
                MMA_BF16(acc[n], a0.x, a1.x, a2.x, a3.x, b0.y, b1.y);
                MMA_BF16(acc[n], a0.y, a1.y, a2.y, a3.y, b0.x, b1.x);
            }
        }
        const int rglob = nbase + r0;
#pragma unroll
        for (int n = 0; n < 4; n++) {
            const int cb = wn * 32 + n * 8 + 2 * tq;
            float o0 = acc[n][0]; o0 = (o0 > 0.0f) ? o0 : 0.01f * o0;
            float o1 = acc[n][1]; o1 = (o1 > 0.0f) ? o1 : 0.01f * o1;
            float o2 = acc[n][2]; o2 = (o2 > 0.0f) ? o2 : 0.01f * o2;
            float o3 = acc[n][3]; o3 = (o3 > 0.0f) ? o3 : 0.01f * o3;
            *reinterpret_cast<float2*>(&out[((size_t)t * N_ + rglob) * OUT_ + cb]) =
                make_float2(o0, o1);
            *reinterpret_cast<float2*>(&out[((size_t)t * N_ + rglob + 8) * OUT_ + cb]) =
                make_float2(o2, o3);
        }
    }
}

// ---------------------------------------------------------------------------
extern "C" void kernel_launch(void* const* d_in, const int* in_sizes, int n_in,
                              void* d_out, int out_size) {
    const float* node = nullptr;
    const float* edge = nullptr;
    const float* w0 = nullptr;
    const float* w1 = nullptr;
    for (int i = 0; i < n_in; i++) {
        const int s = in_sizes[i];
        if (s == T_ * N_ * D_)            node = (const float*)d_in[i];
        else if (s == T_ * E_ * N_ * N_)  edge = (const float*)d_in[i];
        else if (s == H0_ * CIN_)         w0 = (const float*)d_in[i];
        else if (s == OUT_ * H0_)         w1 = (const float*)d_in[i];
    }

    prep_kernel<<<512 + 48, 256>>>(node, w0, w1);

    {
        const size_t smem = (size_t)STAGES * (BM * AS + NC * BSW) * sizeof(unsigned);
        cudaFuncSetAttribute(gemm_edge_kernel,
                             cudaFuncAttributeMaxDynamicSharedMemorySize, (int)smem);
        dim3 grid(GX, T_ * E_);
        gemm_edge_kernel<<<grid, GTHREADS, smem>>>(edge, node);
    }
    {
        const size_t smem = (size_t)(NT * SHS) * sizeof(uint2);
        cudaFuncSetAttribute(mlp_kernel,
                             cudaFuncAttributeMaxDynamicSharedMemorySize, (int)smem);
        mlp_kernel<<<(T_ * N_) / NT, 256, smem>>>((float*)d_out);
    }
}

// round 11
// speedup vs baseline: 2.8710x; 1.0055x over previous
#include <cuda_runtime.h>
#include <cuda_bf16.h>
#include <cstdint>

// Problem constants
#define T_ 4
#define N_ 4096
#define D_ 64
#define E_ 2
#define CIN_ 192
#define H0_ 128
#define OUT_ 64
#define NC 72
#define EPS_ 1e-12f

// GEMM tiling: BM=128, 4 warps x 32 rows, 128 threads; grid 32x8=256 CTAs
#define BM 128
#define GTHREADS 128
#define BK 32
#define AS 40
#define BSW 16                  // B smem row stride in words (k-permuted layout)
#define STAGES 4
#define KT (N_ / BK)
#define GX (N_ / BM)            // 32

// X layout: 96 words (bf16x2 hi/lo pairs) per node
#define XW 96
// MLP tiling
#define NT 64
#define SHS 68
#define W0W 96
#define W1W 64

// Scratch (device globals; no allocation allowed)
__device__ __nv_bfloat16 g_BextB[T_ * NC * N_];  // k-permuted within 32-groups
__device__ uint2 g_Xp[(size_t)T_ * N_ * XW];
__device__ uint2 g_W0p[H0_ * W0W];
__device__ uint2 g_W1p[OUT_ * W1W];

__device__ __forceinline__ void cp16(void* dst_smem, const void* src_gmem) {
    unsigned d = (unsigned)__cvta_generic_to_shared(dst_smem);
    asm volatile("cp.async.cg.shared.global [%0], [%1], 16;\n" :: "r"(d), "l"(src_gmem));
}
__device__ __forceinline__ unsigned packbf(float lo, float hi) {
    unsigned r;
    asm("cvt.rn.bf16x2.f32 %0, %1, %2;" : "=r"(r) : "f"(hi), "f"(lo));
    return r;
}
__device__ __forceinline__ void split2(float x, float y, unsigned& h, unsigned& l) {
    h = packbf(x, y);
    float hx = __uint_as_float(h << 16);
    float hy = __uint_as_float(h & 0xFFFF0000u);
    l = packbf(x - hx, y - hy);
}

#define MMA_BF16(ACC, A0, A1, A2, A3, B0, B1)                                  \
    asm volatile(                                                              \
        "mma.sync.aligned.m16n8k16.row.col.f32.bf16.bf16.f32 "                 \
        "{%0,%1,%2,%3}, {%4,%5,%6,%7}, {%8,%9}, {%0,%1,%2,%3};\n"              \
        : "+f"(ACC[0]), "+f"(ACC[1]), "+f"(ACC[2]), "+f"(ACC[3])               \
        : "r"(A0), "r"(A1), "r"(A2), "r"(A3), "r"(B0), "r"(B1))

// ---------------------------------------------------------------------------
// prep: blocks [0,512): node -> g_BextB (k-permuted) + node part of g_Xp;
//       blocks [512,560): split weights.
// ---------------------------------------------------------------------------
__global__ void __launch_bounds__(256) prep_kernel(const float* __restrict__ node,
                                                   const float* __restrict__ w0,
                                                   const float* __restrict__ w1) {
    const int tid = threadIdx.x;
    if (blockIdx.x >= 512) {
        int i = (blockIdx.x - 512) * 256 + tid;
        if (i < H0_ * W0W) {
            int j = i / W0W, w = i % W0W;
            unsigned h, l;
            split2(w0[(size_t)j * CIN_ + 2 * w], w0[(size_t)j * CIN_ + 2 * w + 1], h, l);
            g_W0p[i] = make_uint2(h, l);
        }
        if (i < OUT_ * W1W) {
            int o = i / W1W, w = i % W1W;
            unsigned h, l;
            split2(w1[(size_t)o * H0_ + 2 * w], w1[(size_t)o * H0_ + 2 * w + 1], h, l);
            g_W1p[i] = make_uint2(h, l);
        }
        return;
    }
    __shared__ float s[32][65];
    const int t = blockIdx.x >> 7;
    const int k0 = (blockIdx.x & 127) * 32;
    for (int i = tid; i < 32 * 64; i += 256) {
        int r = i >> 6, d = i & 63;
        s[r][d] = node[((size_t)t * N_ + k0 + r) * D_ + d];
    }
    __syncthreads();
    for (int o = tid; o < NC * 32; o += 256) {
        int n = o >> 5, kk = o & 31;
        float v = (n < D_) ? s[kk][n] : (n == D_ ? 1.0f : 0.0f);
        const int worig = kk >> 1, b = kk & 1;
        const int kpos = 2 * (4 * (worig & 3) + (worig >> 2)) + b;
        g_BextB[((size_t)t * NC + n) * N_ + k0 + kpos] = __float2bfloat16_rn(v);
    }
    for (int o = tid; o < 32 * 32; o += 256) {
        int r = o >> 5, w = o & 31;
        unsigned h, l;
        split2(s[r][2 * w], s[r][2 * w + 1], h, l);
        g_Xp[((size_t)t * N_ + k0 + r) * XW + w] = make_uint2(h, l);
    }
}

// ---------------------------------------------------------------------------
// Main GEMM + fused normalize epilogue -> split-bf16 g_Xp.
// BM=128, 128 threads (4 warps x 32 rows = 2 m-tiles/warp), 2 CTAs/SM.
// B tile read once per warp-iter, reused across both m-tiles (36 MMAs).
// ---------------------------------------------------------------------------
__global__ void __launch_bounds__(GTHREADS, 2) gemm_edge_kernel(const float* __restrict__ edge,
                                                                const float* __restrict__ node) {
    extern __shared__ unsigned smem[];
    float* sA = reinterpret_cast<float*>(smem);       // [STAGES][BM*AS]
    unsigned* sB = smem + STAGES * BM * AS;           // [STAGES][NC*BSW]

    const int te = blockIdx.y;
    const int t = te / E_;
    const int e = te % E_;
    const int rowBase = blockIdx.x * BM;

    const float* __restrict__ Abase = edge + (size_t)te * N_ * N_;
    const __nv_bfloat16* __restrict__ Bbase = g_BextB + (size_t)t * NC * N_;

    const int tid = threadIdx.x;
    const int warp = tid >> 5;
    const int lane = tid & 31;
    const int g = lane >> 2;
    const int tq = lane & 3;

    const int arow = tid >> 3;          // 0..15
    const int acol = (tid & 7) * 4;

    float acc[2][9][4];
#pragma unroll
    for (int mt = 0; mt < 2; mt++)
#pragma unroll
        for (int j = 0; j < 9; j++)
#pragma unroll
            for (int q = 0; q < 4; q++) acc[mt][j][q] = 0.0f;

    auto load_stage = [&](int s, int k0) {
        float* dA = sA + s * (BM * AS);
        unsigned* dB = sB + s * (NC * BSW);
#pragma unroll
        for (int rr = 0; rr < BM; rr += 16) {
            cp16(&dA[(rr + arow) * AS + acol],
                 Abase + (size_t)(rowBase + rr + arow) * N_ + k0 + acol);
        }
        // B: 72 rows x 64B = 288 16B-chunks
        for (int c = tid; c < NC * 4; c += GTHREADS) {
            int row = c >> 2, ch = c & 3;
            cp16(dB + row * BSW + ch * 4, Bbase + (size_t)row * N_ + k0 + ch * 8);
        }
    };

#pragma unroll
    for (int s = 0; s < STAGES - 1; s++) {
        load_stage(s, s * BK);
        asm volatile("cp.async.commit_group;\n");
    }

    for (int i = 0; i < KT; i++) {
        asm volatile("cp.async.wait_group %0;\n" :: "n"(STAGES - 2));
        __syncthreads();

        const int pf = i + STAGES - 1;
        if (pf < KT) load_stage(pf % STAGES, pf * BK);
        asm volatile("cp.async.commit_group;\n");

        const float* A = sA + (i % STAGES) * (BM * AS);
        const uint4* B4 = reinterpret_cast<const uint4*>(sB + (i % STAGES) * (NC * BSW));

        // A fragments for both m-tiles, both ks
        unsigned a[2][2][4];
#pragma unroll
        for (int mt = 0; mt < 2; mt++) {
            const int r0 = warp * 32 + mt * 16 + g;
#pragma unroll
            for (int ks = 0; ks < 2; ks++) {
                const int kb = ks * 16;
                float2 v;
                v = *reinterpret_cast<const float2*>(&A[r0 * AS + kb + 2 * tq]);
                a[mt][ks][0] = packbf(v.x, v.y);
                v = *reinterpret_cast<const float2*>(&A[(r0 + 8) * AS + kb + 2 * tq]);
                a[mt][ks][1] = packbf(v.x, v.y);
                v = *reinterpret_cast<const float2*>(&A[r0 * AS + kb + 2 * tq + 8]);
                a[mt][ks][2] = packbf(v.x, v.y);
                v = *reinterpret_cast<const float2*>(&A[(r0 + 8) * AS + kb + 2 * tq + 8]);
                a[mt][ks][3] = packbf(v.x, v.y);
            }
        }
#pragma unroll
        for (int j = 0; j < 9; j++) {
            const uint4 bq = B4[(j * 8 + g) * 4 + tq];   // {b0_ks0,b1_ks0,b0_ks1,b1_ks1}
#pragma unroll
            for (int mt = 0; mt < 2; mt++) {
                MMA_BF16(acc[mt][j], a[mt][0][0], a[mt][0][1], a[mt][0][2], a[mt][0][3],
                         bq.x, bq.y);
                MMA_BF16(acc[mt][j], a[mt][1][0], a[mt][1][1], a[mt][1][2], a[mt][1][3],
                         bq.z, bq.w);
            }
        }
    }

    // ---- fused epilogue: normalize + split-bf16 store into g_Xp ----
#pragma unroll
    for (int mt = 0; mt < 2; mt++) {
        const int rg = rowBase + warp * 32 + mt * 16 + g;
        const float rs0 = __shfl_sync(0xffffffffu, acc[mt][8][0], lane & 28);
        const float rs1 = __shfl_sync(0xffffffffu, acc[mt][8][2], lane & 28);
        const float dg0 = __bfloat162float(__float2bfloat16_rn(Abase[(size_t)rg * N_ + rg]));
        const float dg1 = __bfloat162float(__float2bfloat16_rn(Abase[(size_t)(rg + 8) * N_ + rg + 8]));
        const float inv0 = 1.0f / fmaxf(rs0 - dg0, EPS_);
        const float inv1 = 1.0f / fmaxf(rs1 - dg1, EPS_);
        const float* nrow0 = node + ((size_t)t * N_ + rg) * D_;
        const float* nrow1 = node + ((size_t)t * N_ + rg + 8) * D_;
        uint2* X0 = g_Xp + ((size_t)t * N_ + rg) * XW + 32 + 32 * e;
        uint2* X1 = g_Xp + ((size_t)t * N_ + rg + 8) * XW + 32 + 32 * e;
#pragma unroll
        for (int j = 0; j < 8; j++) {
            const int c = j * 8 + tq * 2;
            unsigned h, l;
            float2 nv0 = *reinterpret_cast<const float2*>(nrow0 + c);
            split2((acc[mt][j][0] - dg0 * nv0.x) * inv0,
                   (acc[mt][j][1] - dg0 * nv0.y) * inv0, h, l);
            X0[j * 4 + tq] = make_uint2(h, l);
            float2 nv1 = *reinterpret_cast<const float2*>(nrow1 + c);
            split2((acc[mt][j][2] - dg1 * nv1.x) * inv1,
                   (acc[mt][j][3] - dg1 * nv1.y) * inv1, h, l);
            X1[j * 4 + tq] = make_uint2(h, l);
        }
    }
}

// ---------------------------------------------------------------------------
// MLP: X fragments streamed from gmem (__ldcs) so weights stay L1-resident;
// only H staged in smem.
// ---------------------------------------------------------------------------
__global__ void __launch_bounds__(256, 2) mlp_kernel(float* __restrict__ out) {
    extern __shared__ uint2 smu[];
    uint2* SHp = smu;                 // [NT][SHS]

    const int tid = threadIdx.x;
    const int blk = blockIdx.x;
    const int t = blk / (N_ / NT);
    const int nbase = (blk % (N_ / NT)) * NT;

    const int warp = tid >> 5;
    const int lane = tid & 31;
    const int g = lane >> 2;
    const int tq = lane & 3;
    const int wm = warp & 3;
    const int wn = warp >> 2;
    const int r0 = wm * 16 + g;

    // layer 0
    {
        float acc[8][4];
#pragma unroll
        for (int n = 0; n < 8; n++)
#pragma unroll
            for (int q = 0; q < 4; q++) acc[n][q] = 0.0f;

        const uint2* Xr0 = g_Xp + ((size_t)t * N_ + nbase + r0) * XW;
        const uint2* Xr1 = Xr0 + 8 * XW;
#pragma unroll
        for (int kc = 0; kc < CIN_ / 16; kc++) {
            const uint2 a0 = __ldcs(&Xr0[kc * 8 + tq]);
            const uint2 a1 = __ldcs(&Xr1[kc * 8 + tq]);
            const uint2 a2 = __ldcs(&Xr0[kc * 8 + tq + 4]);
            const uint2 a3 = __ldcs(&Xr1[kc * 8 + tq + 4]);
#pragma unroll
            for (int n = 0; n < 8; n++) {
                const int row = wn * 64 + n * 8 + g;
                const uint2 b0 = g_W0p[row * W0W + kc * 8 + tq];
                const uint2 b1 = g_W0p[row * W0W + kc * 8 + tq + 4];
                MMA_BF16(acc[n], a0.x, a1.x, a2.x, a3.x, b0.x, b1.x);
                MMA_BF16(acc[n], a0.x, a1.x, a2.x, a3.x, b0.y, b1.y);
                MMA_BF16(acc[n], a0.y, a1.y, a2.y, a3.y, b0.x, b1.x);
            }
        }
#pragma unroll
        for (int n = 0; n < 8; n++) {
            const int w = wn * 32 + n * 4 + tq;
            float h0 = acc[n][0]; h0 = (h0 > 0.0f) ? h0 : 0.01f * h0;
            float h1 = acc[n][1]; h1 = (h1 > 0.0f) ? h1 : 0.01f * h1;
            float h2 = acc[n][2]; h2 = (h2 > 0.0f) ? h2 : 0.01f * h2;
            float h3 = acc[n][3]; h3 = (h3 > 0.0f) ? h3 : 0.01f * h3;
            unsigned hh, ll;
            split2(h0, h1, hh, ll);
            SHp[r0 * SHS + w] = make_uint2(hh, ll);
            split2(h2, h3, hh, ll);
            SHp[(r0 + 8) * SHS + w] = make_uint2(hh, ll);
        }
    }
    __syncthreads();

    // layer 1
    {
        float acc[4][4];
#pragma unroll
        for (int n = 0; n < 4; n++)
#pragma unroll
            for (int q = 0; q < 4; q++) acc[n][q] = 0.0f;

#pragma unroll
        for (int kc = 0; kc < H0_ / 16; kc++) {
            const uint2 a0 = SHp[r0 * SHS + kc * 8 + tq];
            const uint2 a1 = SHp[(r0 + 8) * SHS + kc * 8 + tq];
            const uint2 a2 = SHp[r0 * SHS + kc * 8 + tq + 4];
            const uint2 a3 = SHp[(r0 + 8) * SHS + kc * 8 + tq + 4];
#pragma unroll
            for (int n = 0; n < 4; n++) {
                const int row = wn * 32 + n * 8 + g;
                const uint2 b0 = g_W1p[row * W1W + kc * 8 + tq];
                const uint2 b1 = g_W1p[row * W1W + kc * 8 + tq + 4];
                MMA_BF16(acc[n], a0.x, a1.x, a2.x, a3.x, b0.x, b1.x);
                MMA_BF16(acc[n], a0.x, a1.x, a2.x, a3.x, b0.y, b1.y);
                MMA_BF16(acc[n], a0.y, a1.y, a2.y, a3.y, b0.x, b1.x);
            }
        }
        const int rglob = nbase + r0;
#pragma unroll
        for (int n = 0; n < 4; n++) {
            const int cb = wn * 32 + n * 8 + 2 * tq;
            float o0 = acc[n][0]; o0 = (o0 > 0.0f) ? o0 : 0.01f * o0;
            float o1 = acc[n][1]; o1 = (o1 > 0.0f) ? o1 : 0.01f * o1;
            float o2 = acc[n][2]; o2 = (o2 > 0.0f) ? o2 : 0.01f * o2;
            float o3 = acc[n][3]; o3 = (o3 > 0.0f) ? o3 : 0.01f * o3;
            *reinterpret_cast<float2*>(&out[((size_t)t * N_ + rglob) * OUT_ + cb]) =
                make_float2(o0, o1);
            *reinterpret_cast<float2*>(&out[((size_t)t * N_ + rglob + 8) * OUT_ + cb]) =
                make_float2(o2, o3);
        }
    }
}

// ---------------------------------------------------------------------------
extern "C" void kernel_launch(void* const* d_in, const int* in_sizes, int n_in,
                              void* d_out, int out_size) {
    const float* node = nullptr;
    const float* edge = nullptr;
    const float* w0 = nullptr;
    const float* w1 = nullptr;
    for (int i = 0; i < n_in; i++) {
        const int s = in_sizes[i];
        if (s == T_ * N_ * D_)            node = (const float*)d_in[i];
        else if (s == T_ * E_ * N_ * N_)  edge = (const float*)d_in[i];
        else if (s == H0_ * CIN_)         w0 = (const float*)d_in[i];
        else if (s == OUT_ * H0_)         w1 = (const float*)d_in[i];
    }

    prep_kernel<<<512 + 48, 256>>>(node, w0, w1);

    {
        const size_t smem = (size_t)STAGES * (BM * AS + NC * BSW) * sizeof(unsigned);
        cudaFuncSetAttribute(gemm_edge_kernel,
                             cudaFuncAttributeMaxDynamicSharedMemorySize, (int)smem);
        dim3 grid(GX, T_ * E_);
        gemm_edge_kernel<<<grid, GTHREADS, smem>>>(edge, node);
    }
    {
        const size_t smem = (size_t)(NT * SHS) * sizeof(uint2);
        cudaFuncSetAttribute(mlp_kernel,
                             cudaFuncAttributeMaxDynamicSharedMemorySize, (int)smem);
        mlp_kernel<<<(T_ * N_) / NT, 256, smem>>>((float*)d_out);
    }
}